// round 1
// baseline (speedup 1.0000x reference)
#include <cuda_runtime.h>
#include <cuda_bf16.h>

#define T_TOK 4096
#define DIM   1024
#define NE    8
#define CAP   640   // int(1.25 * 4096 / 8)

// ---------------- scratch (no cudaMalloc allowed) ----------------
__device__ int   g_topidx[T_TOK];
__device__ float g_topprob[T_TOK];
__device__ float g_probs[T_TOK * NE];
__device__ int   g_tokens[NE * CAP];
__device__ int   g_m[NE];

// ---------------- zero the output buffer -------------------------
__global__ void zero_out_kernel(float* __restrict__ out, int n) {
    int i = blockIdx.x * blockDim.x + threadIdx.x;
    if (i < n) out[i] = 0.0f;
}

// ---------------- gating: logits, softmax, argmax ----------------
// one warp per token
__global__ void gating_kernel(const float* __restrict__ x,
                              const float* __restrict__ Wg,
                              const float* __restrict__ bg) {
    int warp = (blockIdx.x * blockDim.x + threadIdx.x) >> 5;
    int lane = threadIdx.x & 31;
    if (warp >= T_TOK) return;

    const float* xr = x + (size_t)warp * DIM;
    float acc[NE];
#pragma unroll
    for (int e = 0; e < NE; e++) acc[e] = 0.0f;

    for (int d = lane; d < DIM; d += 32) {
        float xv = xr[d];
        const float4* wg4 = reinterpret_cast<const float4*>(Wg + (size_t)d * NE);
        float4 w0 = wg4[0];
        float4 w1 = wg4[1];
        acc[0] += xv * w0.x; acc[1] += xv * w0.y;
        acc[2] += xv * w0.z; acc[3] += xv * w0.w;
        acc[4] += xv * w1.x; acc[5] += xv * w1.y;
        acc[6] += xv * w1.z; acc[7] += xv * w1.w;
    }
#pragma unroll
    for (int e = 0; e < NE; e++) {
#pragma unroll
        for (int off = 16; off; off >>= 1)
            acc[e] += __shfl_xor_sync(0xffffffffu, acc[e], off);
    }

    if (lane == 0) {
        float l[NE], p[NE];
        float mx = -1e30f;
        int arg = 0;
#pragma unroll
        for (int e = 0; e < NE; e++) l[e] = acc[e] + bg[e];
#pragma unroll
        for (int e = 0; e < NE; e++) {
            if (l[e] > mx) { mx = l[e]; arg = e; }
        }
        float s = 0.0f;
#pragma unroll
        for (int e = 0; e < NE; e++) { p[e] = expf(l[e] - mx); s += p[e]; }
        float inv = 1.0f / s;
#pragma unroll
        for (int e = 0; e < NE; e++) g_probs[(size_t)warp * NE + e] = p[e] * inv;
        g_topidx[warp]  = arg;
        g_topprob[warp] = p[arg] * inv;
    }
}

// ---------------- routing scan (one block) -----------------------
// computes per-expert positions (capacity mask), compacted token lists,
// kept counts, and the aux load-balance loss (deterministic reduction).
__global__ void __launch_bounds__(1024) route_kernel(float* __restrict__ aux_out) {
    __shared__ int sm[1024][NE];   // 32 KB
    int tid = threadIdx.x;

    int local[NE];
#pragma unroll
    for (int e = 0; e < NE; e++) local[e] = 0;
    int myexp[4];
#pragma unroll
    for (int j = 0; j < 4; j++) {
        int t = tid * 4 + j;
        int e = g_topidx[t];
        myexp[j] = e;
        local[e]++;
    }
#pragma unroll
    for (int e = 0; e < NE; e++) sm[tid][e] = local[e];
    __syncthreads();

    // Hillis-Steele inclusive scan over 1024 threads of 8-vectors
    for (int off = 1; off < 1024; off <<= 1) {
        int add[NE];
#pragma unroll
        for (int e = 0; e < NE; e++) add[e] = (tid >= off) ? sm[tid - off][e] : 0;
        __syncthreads();
#pragma unroll
        for (int e = 0; e < NE; e++) sm[tid][e] += add[e];
        __syncthreads();
    }

    int total[NE];
#pragma unroll
    for (int e = 0; e < NE; e++) total[e] = sm[1023][e];

    int run[NE];
#pragma unroll
    for (int e = 0; e < NE; e++) run[e] = sm[tid][e] - local[e];  // exclusive prefix

#pragma unroll
    for (int j = 0; j < 4; j++) {
        int t = tid * 4 + j;
        int e = myexp[j];
        run[e]++;
        int pos = run[e];             // 1-indexed position within expert buffer
        if (pos <= CAP) g_tokens[e * CAP + pos - 1] = t;
    }
    if (tid < NE) g_m[tid] = (total[tid] < CAP) ? total[tid] : CAP;
    __syncthreads();

    // deterministic reduction of prob sums for aux loss (reuse smem as float)
    float* fsm = reinterpret_cast<float*>(sm);
    float lp[NE];
#pragma unroll
    for (int e = 0; e < NE; e++) lp[e] = 0.0f;
#pragma unroll
    for (int j = 0; j < 4; j++) {
        int t = tid * 4 + j;
#pragma unroll
        for (int e = 0; e < NE; e++) lp[e] += g_probs[(size_t)t * NE + e];
    }
#pragma unroll
    for (int e = 0; e < NE; e++) fsm[tid * NE + e] = lp[e];
    __syncthreads();
    for (int off = 512; off >= 1; off >>= 1) {
        if (tid < off) {
#pragma unroll
            for (int e = 0; e < NE; e++)
                fsm[tid * NE + e] += fsm[(tid + off) * NE + e];
        }
        __syncthreads();
    }
    if (tid == 0 && aux_out != nullptr) {
        float aux = 0.0f;
        const float invT = 1.0f / (float)T_TOK;
#pragma unroll
        for (int e = 0; e < NE; e++) {
            float f = (float)total[e] * invT;
            float P = fsm[e] * invT;
            aux += f * P;
        }
        *aux_out = (float)NE * aux;
    }
}

// ---------------- per-expert gathered GEMM -----------------------
// out[tok,:] = (x[tok,:] @ W[e] + b[e]) * top_prob[tok] for kept tokens.
// BM=64, BN=64, BK=16, 256 threads, 4x4 microtile.
#define BM 64
#define BN 64
#define BK 16

__global__ void __launch_bounds__(256) expert_gemm_kernel(
        const float* __restrict__ x, const float* __restrict__ W,
        const float* __restrict__ bias, float* __restrict__ out) {
    int e    = blockIdx.z;
    int m    = g_m[e];
    int row0 = blockIdx.y * BM;
    if (row0 >= m) return;
    int col0 = blockIdx.x * BN;

    __shared__ float As[BK][BM + 4];   // +4 pad: keeps float4 alignment, reduces conflicts
    __shared__ float Bs[BK][BN];
    __shared__ int   stok[BM];
    __shared__ float sprob[BM];

    int tid = threadIdx.x;
    if (tid < BM) {
        int gr  = row0 + tid;
        int tok = (gr < m) ? g_tokens[e * CAP + gr] : 0;
        stok[tid]  = tok;
        sprob[tid] = (gr < m) ? g_topprob[tok] : 0.0f;
    }
    __syncthreads();

    int tx = tid & 15;    // col group (x4)
    int ty = tid >> 4;    // row group (x4)

    // A-tile load mapping: row = tid/4, k-quad = tid%4
    int ar  = tid >> 2;
    int akq = tid & 3;
    bool arow_ok = (row0 + ar) < m;
    const float* aptr = x + (size_t)stok[ar] * DIM;

    // B-tile load mapping: k-row = tid/16, n-quad = tid%16
    int bkr = tid >> 4;
    int bnq = tid & 15;
    const float* wbase = W + (size_t)e * DIM * DIM + col0;

    float acc[4][4];
#pragma unroll
    for (int i = 0; i < 4; i++)
#pragma unroll
        for (int j = 0; j < 4; j++) acc[i][j] = 0.0f;

    for (int k0 = 0; k0 < DIM; k0 += BK) {
        float4 av = arow_ok
            ? *reinterpret_cast<const float4*>(aptr + k0 + akq * 4)
            : make_float4(0.f, 0.f, 0.f, 0.f);
        As[akq * 4 + 0][ar] = av.x;
        As[akq * 4 + 1][ar] = av.y;
        As[akq * 4 + 2][ar] = av.z;
        As[akq * 4 + 3][ar] = av.w;

        float4 bv = *reinterpret_cast<const float4*>(
            wbase + (size_t)(k0 + bkr) * DIM + bnq * 4);
        *reinterpret_cast<float4*>(&Bs[bkr][bnq * 4]) = bv;

        __syncthreads();
#pragma unroll
        for (int k = 0; k < BK; k++) {
            float4 a4 = *reinterpret_cast<const float4*>(&As[k][ty * 4]);
            float4 b4 = *reinterpret_cast<const float4*>(&Bs[k][tx * 4]);
            acc[0][0] += a4.x * b4.x; acc[0][1] += a4.x * b4.y;
            acc[0][2] += a4.x * b4.z; acc[0][3] += a4.x * b4.w;
            acc[1][0] += a4.y * b4.x; acc[1][1] += a4.y * b4.y;
            acc[1][2] += a4.y * b4.z; acc[1][3] += a4.y * b4.w;
            acc[2][0] += a4.z * b4.x; acc[2][1] += a4.z * b4.y;
            acc[2][2] += a4.z * b4.z; acc[2][3] += a4.z * b4.w;
            acc[3][0] += a4.w * b4.x; acc[3][1] += a4.w * b4.y;
            acc[3][2] += a4.w * b4.z; acc[3][3] += a4.w * b4.w;
        }
        __syncthreads();
    }

    // epilogue: add bias, scale by top_prob, scatter to out rows
    int col = col0 + tx * 4;
    float4 bb = *reinterpret_cast<const float4*>(bias + (size_t)e * DIM + col);
#pragma unroll
    for (int i = 0; i < 4; i++) {
        int gr = row0 + ty * 4 + i;
        if (gr >= m) continue;
        int   tok = stok[ty * 4 + i];
        float p   = sprob[ty * 4 + i];
        float4 o;
        o.x = (acc[i][0] + bb.x) * p;
        o.y = (acc[i][1] + bb.y) * p;
        o.z = (acc[i][2] + bb.z) * p;
        o.w = (acc[i][3] + bb.w) * p;
        *reinterpret_cast<float4*>(out + (size_t)tok * DIM + col) = o;
    }
}

// ---------------- launch ----------------
extern "C" void kernel_launch(void* const* d_in, const int* in_sizes, int n_in,
                              void* d_out, int out_size) {
    const float* x  = (const float*)d_in[0];   // [T, D]
    const float* Wg = (const float*)d_in[1];   // [D, E]
    const float* bg = (const float*)d_in[2];   // [E]
    const float* W  = (const float*)d_in[3];   // [E, D, D]
    const float* b  = (const float*)d_in[4];   // [E, D]
    float* out = (float*)d_out;

    // zero the whole output (dropped tokens must be 0; buffer is poisoned)
    {
        int n = out_size;
        int blocks = (n + 255) / 256;
        zero_out_kernel<<<blocks, 256>>>(out, n);
    }

    // gating: one warp per token -> 4096 warps = 512 blocks of 256
    gating_kernel<<<(T_TOK * 32 + 255) / 256, 256>>>(x, Wg, bg);

    // routing scan + aux loss
    float* aux_out = (out_size > T_TOK * DIM) ? (out + (size_t)T_TOK * DIM) : nullptr;
    route_kernel<<<1, 1024>>>(aux_out);

    // per-expert gathered GEMM
    dim3 grid(DIM / BN, (CAP + BM - 1) / BM, NE);
    expert_gemm_kernel<<<grid, 256>>>(x, W, b, out);
}

// round 3
// speedup vs baseline: 1.6049x; 1.6049x over previous
#include <cuda_runtime.h>
#include <cuda_bf16.h>
#include <cstdint>

#define T_TOK 4096
#define DIM   1024
#define NE    8
#define CAP   640   // int(1.25 * 4096 / 8)

// ---------------- scratch (no cudaMalloc allowed) ----------------
__device__ int   g_topidx[T_TOK];
__device__ float g_topprob[T_TOK];
__device__ float g_probs[T_TOK * NE];
__device__ int   g_tokens[NE * CAP];
__device__ int   g_m[NE];

// bf16 split operands
__device__ __nv_bfloat16 g_xhi[T_TOK * DIM];                 // 8 MB
__device__ __nv_bfloat16 g_xlo[T_TOK * DIM];                 // 8 MB
__device__ __nv_bfloat16 g_wth[NE * DIM * DIM];              // 16 MB  W^T hi : [e][n][k]
__device__ __nv_bfloat16 g_wtl[NE * DIM * DIM];              // 16 MB  W^T lo

// ---------------- helpers ----------------
__device__ __forceinline__ uint32_t smem_u32(const void* p) {
    uint32_t a;
    asm("{ .reg .u64 t; cvta.to.shared.u64 t, %1; cvt.u32.u64 %0, t; }" : "=r"(a) : "l"(p));
    return a;
}
__device__ __forceinline__ void cpasync16(uint32_t dst, const void* src) {
    asm volatile("cp.async.cg.shared.global [%0], [%1], 16;"
                 :: "r"(dst), "l"(__cvta_generic_to_global(src)) : "memory");
}
__device__ __forceinline__ void cp_commit() {
    asm volatile("cp.async.commit_group;" ::: "memory");
}
__device__ __forceinline__ void cp_wait_all() {
    asm volatile("cp.async.wait_group 0;" ::: "memory");
}
#define LDSM4(r0, r1, r2, r3, a)                                             \
    asm volatile("ldmatrix.sync.aligned.m8n8.x4.shared.b16 {%0,%1,%2,%3}, [%4];" \
                 : "=r"(r0), "=r"(r1), "=r"(r2), "=r"(r3) : "r"(a))
#define MMA16816(d, a, b0v, b1v)                                             \
    asm volatile("mma.sync.aligned.m16n8k16.row.col.f32.bf16.bf16.f32 "      \
                 "{%0,%1,%2,%3},{%4,%5,%6,%7},{%8,%9},{%0,%1,%2,%3};"        \
                 : "+f"((d)[0]), "+f"((d)[1]), "+f"((d)[2]), "+f"((d)[3])    \
                 : "r"((a)[0]), "r"((a)[1]), "r"((a)[2]), "r"((a)[3]),       \
                   "r"(b0v), "r"(b1v))

// ---------------- zero the output buffer -------------------------
__global__ void zero_out_kernel(float* __restrict__ out, int n) {
    int i = blockIdx.x * blockDim.x + threadIdx.x;
    if (i < n) out[i] = 0.0f;
}

// ---------------- split x into bf16 hi/lo ------------------------
__global__ void convert_x_kernel(const float* __restrict__ x) {
    int i = blockIdx.x * blockDim.x + threadIdx.x;  // one float4 per thread
    float4 v = reinterpret_cast<const float4*>(x)[i];
    __nv_bfloat16 h[4], l[4];
    float f[4] = {v.x, v.y, v.z, v.w};
#pragma unroll
    for (int j = 0; j < 4; j++) {
        h[j] = __float2bfloat16(f[j]);
        l[j] = __float2bfloat16(f[j] - __bfloat162float(h[j]));
    }
    reinterpret_cast<uint2*>(g_xhi)[i] = *reinterpret_cast<uint2*>(h);
    reinterpret_cast<uint2*>(g_xlo)[i] = *reinterpret_cast<uint2*>(l);
}

// ---------------- split + transpose W -> W^T bf16 hi/lo ----------
__global__ void convert_w_kernel(const float* __restrict__ W) {
    __shared__ float t[32][33];
    int e  = blockIdx.z;
    int kb = blockIdx.y * 32;
    int nb = blockIdx.x * 32;
    int tx = threadIdx.x, ty = threadIdx.y;   // block (32, 8)
    const float* we = W + (size_t)e * DIM * DIM;
#pragma unroll
    for (int j = 0; j < 32; j += 8)
        t[ty + j][tx] = we[(size_t)(kb + ty + j) * DIM + nb + tx];
    __syncthreads();
#pragma unroll
    for (int j = 0; j < 32; j += 8) {
        int n = nb + ty + j;
        int k = kb + tx;
        float v = t[tx][ty + j];   // = W[e][k][n]
        __nv_bfloat16 h = __float2bfloat16(v);
        __nv_bfloat16 l = __float2bfloat16(v - __bfloat162float(h));
        size_t idx = (size_t)e * DIM * DIM + (size_t)n * DIM + k;
        g_wth[idx] = h;
        g_wtl[idx] = l;
    }
}

// ---------------- gating: logits, softmax, argmax ----------------
__global__ void gating_kernel(const float* __restrict__ x,
                              const float* __restrict__ Wg,
                              const float* __restrict__ bg) {
    int warp = (blockIdx.x * blockDim.x + threadIdx.x) >> 5;
    int lane = threadIdx.x & 31;
    if (warp >= T_TOK) return;

    const float* xr = x + (size_t)warp * DIM;
    float acc[NE];
#pragma unroll
    for (int e = 0; e < NE; e++) acc[e] = 0.0f;

    for (int d = lane; d < DIM; d += 32) {
        float xv = xr[d];
        const float4* wg4 = reinterpret_cast<const float4*>(Wg + (size_t)d * NE);
        float4 w0 = wg4[0];
        float4 w1 = wg4[1];
        acc[0] += xv * w0.x; acc[1] += xv * w0.y;
        acc[2] += xv * w0.z; acc[3] += xv * w0.w;
        acc[4] += xv * w1.x; acc[5] += xv * w1.y;
        acc[6] += xv * w1.z; acc[7] += xv * w1.w;
    }
#pragma unroll
    for (int e = 0; e < NE; e++) {
#pragma unroll
        for (int off = 16; off; off >>= 1)
            acc[e] += __shfl_xor_sync(0xffffffffu, acc[e], off);
    }

    if (lane == 0) {
        float l[NE], p[NE];
        float mx = -1e30f;
        int arg = 0;
#pragma unroll
        for (int e = 0; e < NE; e++) l[e] = acc[e] + bg[e];
#pragma unroll
        for (int e = 0; e < NE; e++) {
            if (l[e] > mx) { mx = l[e]; arg = e; }
        }
        float s = 0.0f;
#pragma unroll
        for (int e = 0; e < NE; e++) { p[e] = expf(l[e] - mx); s += p[e]; }
        float inv = 1.0f / s;
#pragma unroll
        for (int e = 0; e < NE; e++) g_probs[(size_t)warp * NE + e] = p[e] * inv;
        g_topidx[warp]  = arg;
        g_topprob[warp] = p[arg] * inv;
    }
}

// ---------------- routing scan (one block) -----------------------
__global__ void __launch_bounds__(1024) route_kernel(float* __restrict__ aux_out) {
    __shared__ int sm[1024][NE];   // 32 KB
    int tid = threadIdx.x;

    int local[NE];
#pragma unroll
    for (int e = 0; e < NE; e++) local[e] = 0;
    int myexp[4];
#pragma unroll
    for (int j = 0; j < 4; j++) {
        int t = tid * 4 + j;
        int e = g_topidx[t];
        myexp[j] = e;
        local[e]++;
    }
#pragma unroll
    for (int e = 0; e < NE; e++) sm[tid][e] = local[e];
    __syncthreads();

    for (int off = 1; off < 1024; off <<= 1) {
        int add[NE];
#pragma unroll
        for (int e = 0; e < NE; e++) add[e] = (tid >= off) ? sm[tid - off][e] : 0;
        __syncthreads();
#pragma unroll
        for (int e = 0; e < NE; e++) sm[tid][e] += add[e];
        __syncthreads();
    }

    int total[NE];
#pragma unroll
    for (int e = 0; e < NE; e++) total[e] = sm[1023][e];

    int run[NE];
#pragma unroll
    for (int e = 0; e < NE; e++) run[e] = sm[tid][e] - local[e];

#pragma unroll
    for (int j = 0; j < 4; j++) {
        int t = tid * 4 + j;
        int e = myexp[j];
        run[e]++;
        int pos = run[e];
        if (pos <= CAP) g_tokens[e * CAP + pos - 1] = t;
    }
    if (tid < NE) g_m[tid] = (total[tid] < CAP) ? total[tid] : CAP;
    __syncthreads();

    float* fsm = reinterpret_cast<float*>(sm);
    float lp[NE];
#pragma unroll
    for (int e = 0; e < NE; e++) lp[e] = 0.0f;
#pragma unroll
    for (int j = 0; j < 4; j++) {
        int t = tid * 4 + j;
#pragma unroll
        for (int e = 0; e < NE; e++) lp[e] += g_probs[(size_t)t * NE + e];
    }
#pragma unroll
    for (int e = 0; e < NE; e++) fsm[tid * NE + e] = lp[e];
    __syncthreads();
    for (int off = 512; off >= 1; off >>= 1) {
        if (tid < off) {
#pragma unroll
            for (int e = 0; e < NE; e++)
                fsm[tid * NE + e] += fsm[(tid + off) * NE + e];
        }
        __syncthreads();
    }
    if (tid == 0 && aux_out != nullptr) {
        float aux = 0.0f;
        const float invT = 1.0f / (float)T_TOK;
#pragma unroll
        for (int e = 0; e < NE; e++) {
            float f = (float)total[e] * invT;
            float P = fsm[e] * invT;
            aux += f * P;
        }
        *aux_out = (float)NE * aux;
    }
}

// ---------------- HMMA gathered expert GEMM ----------------------
// block 128x128x32, 8 warps (4 M x 2 N), warp tile 32x64.
// acc = Ahi*Bhi + Ahi*Blo + Alo*Bhi  (bf16 split-2, fp32 accum)
#define GBM 128
#define GBN 128
#define GBK 32
#define NITER (DIM / GBK)          // 32
#define TILE_BYTES 8192            // 128 rows x 32 bf16
#define STAGE_BYTES (4 * TILE_BYTES)   // Ahi, Alo, Bhi, Blo
#define SMEM_DATA0 1024
#define SMEM_GEMM (SMEM_DATA0 + 2 * STAGE_BYTES)   // 66560

// swizzled in-tile byte offset for (row, k): 64B rows, 16B chunks XOR'd
__device__ __forceinline__ uint32_t sw_off(int row, int kb) {
    return (uint32_t)(row * 64 + ((kb ^ ((row >> 1) & 3)) << 4));
}

__global__ void __launch_bounds__(256, 1) moe_hmma_kernel(
        const float* __restrict__ bias, float* __restrict__ out) {
    int e    = blockIdx.z;
    int m    = g_m[e];
    int row0 = blockIdx.y * GBM;
    if (row0 >= m) return;
    int col0 = blockIdx.x * GBN;

    extern __shared__ char smem[];
    uint32_t sb = smem_u32(smem);
    int tid  = threadIdx.x;
    int wid  = tid >> 5;
    int lane = tid & 31;
    int warp_m = wid & 3;       // 0..3 -> m offset *32
    int warp_n = wid >> 2;      // 0..1 -> n offset *64

    int*   stok  = reinterpret_cast<int*>(smem);          // [128]
    float* sprob = reinterpret_cast<float*>(smem + 512);  // [128]

    if (tid < GBM) {
        int gr  = row0 + tid;
        int tok = (gr < m) ? g_tokens[e * CAP + gr] : 0;
        stok[tid]  = tok;
        sprob[tid] = (gr < m) ? g_topprob[tok] : 0.0f;
    }
    __syncthreads();

    const __nv_bfloat16* wh = g_wth + ((size_t)e * DIM + col0) * DIM;
    const __nv_bfloat16* wl = g_wtl + ((size_t)e * DIM + col0) * DIM;

    // loader mapping: 2 chunks per tile per thread
    int c0 = tid,        r0c = c0 >> 2, k0c = c0 & 3;
    int c1 = tid + 256,  r1c = c1 >> 2, k1c = c1 & 3;
    uint32_t d0 = sw_off(r0c, k0c);
    uint32_t d1 = sw_off(r1c, k1c);
    size_t a0row = (size_t)stok[r0c] * DIM;
    size_t a1row = (size_t)stok[r1c] * DIM;
    size_t b0row = (size_t)r0c * DIM;
    size_t b1row = (size_t)r1c * DIM;

#define ISSUE_STAGE(S, KC0)                                                   \
    do {                                                                      \
        uint32_t st = sb + SMEM_DATA0 + (uint32_t)(S) * STAGE_BYTES;          \
        int ka0 = (KC0) + k0c * 8, ka1 = (KC0) + k1c * 8;                     \
        cpasync16(st + d0,                  g_xhi + a0row + ka0);             \
        cpasync16(st + d1,                  g_xhi + a1row + ka1);             \
        cpasync16(st + TILE_BYTES + d0,     g_xlo + a0row + ka0);             \
        cpasync16(st + TILE_BYTES + d1,     g_xlo + a1row + ka1);             \
        cpasync16(st + 2 * TILE_BYTES + d0, wh + b0row + ka0);                \
        cpasync16(st + 2 * TILE_BYTES + d1, wh + b1row + ka1);                \
        cpasync16(st + 3 * TILE_BYTES + d0, wl + b0row + ka0);                \
        cpasync16(st + 3 * TILE_BYTES + d1, wl + b1row + ka1);                \
        cp_commit();                                                          \
    } while (0)

    // precomputed ldmatrix lane offsets
    int q = lane >> 3, r = lane & 7;
    uint32_t a_off[2][2], b_off[4][2];
#pragma unroll
    for (int mt = 0; mt < 2; mt++)
#pragma unroll
        for (int ks = 0; ks < 2; ks++) {
            int mm = warp_m * 32 + mt * 16 + (q & 1) * 8 + r;
            int kb = ks * 2 + (q >> 1);
            a_off[mt][ks] = sw_off(mm, kb);
        }
#pragma unroll
    for (int nt2 = 0; nt2 < 4; nt2++)
#pragma unroll
        for (int ks = 0; ks < 2; ks++) {
            int nn = warp_n * 64 + nt2 * 16 + (q & 1) * 8 + r;
            int kb = ks * 2 + (q >> 1);
            b_off[nt2][ks] = sw_off(nn, kb);
        }

    float acc[2][8][4];
#pragma unroll
    for (int mt = 0; mt < 2; mt++)
#pragma unroll
        for (int nt = 0; nt < 8; nt++)
#pragma unroll
            for (int j = 0; j < 4; j++) acc[mt][nt][j] = 0.0f;

    ISSUE_STAGE(0, 0);

    for (int c = 0; c < NITER; c++) {
        cp_wait_all();
        __syncthreads();
        if (c + 1 < NITER) ISSUE_STAGE((c + 1) & 1, (c + 1) * GBK);

        uint32_t st = sb + SMEM_DATA0 + (uint32_t)(c & 1) * STAGE_BYTES;
#pragma unroll
        for (int ks = 0; ks < 2; ks++) {
            uint32_t ah[2][4], al[2][4];
#pragma unroll
            for (int mt = 0; mt < 2; mt++) {
                LDSM4(ah[mt][0], ah[mt][1], ah[mt][2], ah[mt][3], st + a_off[mt][ks]);
                LDSM4(al[mt][0], al[mt][1], al[mt][2], al[mt][3], st + TILE_BYTES + a_off[mt][ks]);
            }
            uint32_t bh[8][2], bl[8][2];
#pragma unroll
            for (int nt2 = 0; nt2 < 4; nt2++) {
                uint32_t t0, t1, t2, t3;
                LDSM4(t0, t1, t2, t3, st + 2 * TILE_BYTES + b_off[nt2][ks]);
                bh[nt2 * 2][0] = t0; bh[nt2 * 2][1] = t2;
                bh[nt2 * 2 + 1][0] = t1; bh[nt2 * 2 + 1][1] = t3;
                LDSM4(t0, t1, t2, t3, st + 3 * TILE_BYTES + b_off[nt2][ks]);
                bl[nt2 * 2][0] = t0; bl[nt2 * 2][1] = t2;
                bl[nt2 * 2 + 1][0] = t1; bl[nt2 * 2 + 1][1] = t3;
            }
#pragma unroll
            for (int mt = 0; mt < 2; mt++)
#pragma unroll
                for (int nt = 0; nt < 8; nt++)
                    MMA16816(acc[mt][nt], ah[mt], bh[nt][0], bh[nt][1]);
#pragma unroll
            for (int mt = 0; mt < 2; mt++)
#pragma unroll
                for (int nt = 0; nt < 8; nt++)
                    MMA16816(acc[mt][nt], ah[mt], bl[nt][0], bl[nt][1]);
#pragma unroll
            for (int mt = 0; mt < 2; mt++)
#pragma unroll
                for (int nt = 0; nt < 8; nt++)
                    MMA16816(acc[mt][nt], al[mt], bh[nt][0], bh[nt][1]);
        }
        __syncthreads();
    }

    // epilogue: scatter with bias + prob scale
    int tq = lane >> 2;          // row within 8
    int tr = lane & 3;           // col pair
    const float* be = bias + (size_t)e * DIM;
#pragma unroll
    for (int nt = 0; nt < 8; nt++) {
        int col = col0 + warp_n * 64 + nt * 8 + tr * 2;
        float2 bb = *reinterpret_cast<const float2*>(be + col);
#pragma unroll
        for (int mt = 0; mt < 2; mt++) {
#pragma unroll
            for (int h = 0; h < 2; h++) {
                int rw = warp_m * 32 + mt * 16 + h * 8 + tq;
                int gr = row0 + rw;
                if (gr < m) {
                    int   tok = stok[rw];
                    float p   = sprob[rw];
                    float2 o;
                    o.x = (acc[mt][nt][h * 2 + 0] + bb.x) * p;
                    o.y = (acc[mt][nt][h * 2 + 1] + bb.y) * p;
                    *reinterpret_cast<float2*>(out + (size_t)tok * DIM + col) = o;
                }
            }
        }
    }
}

// ---------------- launch ----------------
extern "C" void kernel_launch(void* const* d_in, const int* in_sizes, int n_in,
                              void* d_out, int out_size) {
    const float* x  = (const float*)d_in[0];   // [T, D]
    const float* Wg = (const float*)d_in[1];   // [D, E]
    const float* bg = (const float*)d_in[2];   // [E]
    const float* W  = (const float*)d_in[3];   // [E, D, D]
    const float* b  = (const float*)d_in[4];   // [E, D]
    float* out = (float*)d_out;

    zero_out_kernel<<<(out_size + 255) / 256, 256>>>(out, out_size);

    convert_x_kernel<<<(T_TOK * DIM / 4 + 255) / 256, 256>>>(x);
    {
        dim3 grid(DIM / 32, DIM / 32, NE);
        dim3 blk(32, 8);
        convert_w_kernel<<<grid, blk>>>(W);
    }

    gating_kernel<<<(T_TOK * 32 + 255) / 256, 256>>>(x, Wg, bg);

    float* aux_out = (out_size > T_TOK * DIM) ? (out + (size_t)T_TOK * DIM) : nullptr;
    route_kernel<<<1, 1024>>>(aux_out);

    cudaFuncSetAttribute(moe_hmma_kernel,
                         cudaFuncAttributeMaxDynamicSharedMemorySize, SMEM_GEMM);
    dim3 grid(DIM / GBN, (CAP + GBM - 1) / GBM, NE);
    moe_hmma_kernel<<<grid, 256, SMEM_GEMM>>>(b, out);
}

// round 4
// speedup vs baseline: 2.2807x; 1.4211x over previous
#include <cuda_runtime.h>
#include <cuda_fp16.h>
#include <cstdint>

#define T_TOK 4096
#define DIM   1024
#define NE    8
#define CAP   640   // int(1.25 * 4096 / 8)

// ---------------- scratch (no cudaMalloc allowed) ----------------
__device__ int   g_topidx[T_TOK];
__device__ float g_topprob[T_TOK];
__device__ float g_probs[T_TOK * NE];
__device__ int   g_tokens[NE * CAP];
__device__ int   g_m[NE];
__device__ int   g_kept[T_TOK];

// fp16 operands: x split hi/lo, W^T single fp16
__device__ __half g_xhi[T_TOK * DIM];        // 8 MB
__device__ __half g_xlo[T_TOK * DIM];        // 8 MB
__device__ __half g_wt[NE * DIM * DIM];      // 16 MB  W^T : [e][n][k]

// ---------------- helpers ----------------
__device__ __forceinline__ uint32_t smem_u32(const void* p) {
    uint32_t a;
    asm("{ .reg .u64 t; cvta.to.shared.u64 t, %1; cvt.u32.u64 %0, t; }" : "=r"(a) : "l"(p));
    return a;
}
__device__ __forceinline__ void cpasync16(uint32_t dst, const void* src) {
    asm volatile("cp.async.cg.shared.global [%0], [%1], 16;"
                 :: "r"(dst), "l"(__cvta_generic_to_global(src)) : "memory");
}
__device__ __forceinline__ void cp_commit() {
    asm volatile("cp.async.commit_group;" ::: "memory");
}
__device__ __forceinline__ void cp_wait_all() {
    asm volatile("cp.async.wait_group 0;" ::: "memory");
}
#define LDSM4(r0, r1, r2, r3, a)                                             \
    asm volatile("ldmatrix.sync.aligned.m8n8.x4.shared.b16 {%0,%1,%2,%3}, [%4];" \
                 : "=r"(r0), "=r"(r1), "=r"(r2), "=r"(r3) : "r"(a))
#define MMA16816(d, a, b0v, b1v)                                             \
    asm volatile("mma.sync.aligned.m16n8k16.row.col.f32.f16.f16.f32 "        \
                 "{%0,%1,%2,%3},{%4,%5,%6,%7},{%8,%9},{%0,%1,%2,%3};"        \
                 : "+f"((d)[0]), "+f"((d)[1]), "+f"((d)[2]), "+f"((d)[3])    \
                 : "r"((a)[0]), "r"((a)[1]), "r"((a)[2]), "r"((a)[3]),       \
                   "r"(b0v), "r"(b1v))

// ---------------- fused gating + x split (one warp / token) ------
__global__ void gating_split_kernel(const float* __restrict__ x,
                                    const float* __restrict__ Wg,
                                    const float* __restrict__ bg) {
    int warp = (blockIdx.x * blockDim.x + threadIdx.x) >> 5;
    int lane = threadIdx.x & 31;
    if (warp >= T_TOK) return;

    const float4* xr4 = reinterpret_cast<const float4*>(x + (size_t)warp * DIM);
    float acc[NE];
#pragma unroll
    for (int e = 0; e < NE; e++) acc[e] = 0.0f;

#pragma unroll
    for (int j = 0; j < 8; j++) {
        int d = j * 128 + lane * 4;
        float4 v = xr4[d >> 2];
        float f[4] = {v.x, v.y, v.z, v.w};
        __half h[4], l[4];
#pragma unroll
        for (int i = 0; i < 4; i++) {
            h[i] = __float2half(f[i]);
            l[i] = __float2half(f[i] - __half2float(h[i]));
            const float4* wg4 = reinterpret_cast<const float4*>(Wg + (size_t)(d + i) * NE);
            float4 w0 = wg4[0];
            float4 w1 = wg4[1];
            acc[0] += f[i] * w0.x; acc[1] += f[i] * w0.y;
            acc[2] += f[i] * w0.z; acc[3] += f[i] * w0.w;
            acc[4] += f[i] * w1.x; acc[5] += f[i] * w1.y;
            acc[6] += f[i] * w1.z; acc[7] += f[i] * w1.w;
        }
        size_t o = (size_t)warp * DIM + d;
        *reinterpret_cast<uint2*>(g_xhi + o) = *reinterpret_cast<uint2*>(h);
        *reinterpret_cast<uint2*>(g_xlo + o) = *reinterpret_cast<uint2*>(l);
    }
#pragma unroll
    for (int e = 0; e < NE; e++) {
#pragma unroll
        for (int off = 16; off; off >>= 1)
            acc[e] += __shfl_xor_sync(0xffffffffu, acc[e], off);
    }

    if (lane == 0) {
        float l[NE], p[NE];
        float mx = -1e30f;
        int arg = 0;
#pragma unroll
        for (int e = 0; e < NE; e++) l[e] = acc[e] + bg[e];
#pragma unroll
        for (int e = 0; e < NE; e++) {
            if (l[e] > mx) { mx = l[e]; arg = e; }
        }
        float s = 0.0f;
#pragma unroll
        for (int e = 0; e < NE; e++) { p[e] = expf(l[e] - mx); s += p[e]; }
        float inv = 1.0f / s;
#pragma unroll
        for (int e = 0; e < NE; e++) g_probs[(size_t)warp * NE + e] = p[e] * inv;
        g_topidx[warp]  = arg;
        g_topprob[warp] = p[arg] * inv;
    }
}

// ---------------- W transpose + fp16 convert ---------------------
// W[e][k][n] -> g_wt[e][n][k]
__global__ void convert_w_kernel(const float* __restrict__ W) {
    __shared__ float t[32][33];
    int e  = blockIdx.z;
    int kb = blockIdx.y * 32;
    int nb = blockIdx.x * 32;
    int tx = threadIdx.x, ty = threadIdx.y;   // block (32, 8)
    const float* we = W + (size_t)e * DIM * DIM;
#pragma unroll
    for (int j = 0; j < 32; j += 8)
        t[ty + j][tx] = we[(size_t)(kb + ty + j) * DIM + nb + tx];
    __syncthreads();
#pragma unroll
    for (int j = 0; j < 32; j += 8) {
        int n = nb + ty + j;
        int k = kb + tx;
        g_wt[(size_t)e * DIM * DIM + (size_t)n * DIM + k] = __float2half(t[tx][ty + j]);
    }
}

// ---------------- routing scan (shfl-based) ----------------------
__global__ void __launch_bounds__(1024) route_kernel(float* __restrict__ aux_out) {
    __shared__ int   wtot[32][NE];
    __shared__ float wsum[32][NE];
    int tid  = threadIdx.x;
    int lane = tid & 31;
    int warp = tid >> 5;

    int c[NE];
#pragma unroll
    for (int e = 0; e < NE; e++) c[e] = 0;
    int myexp[4];
#pragma unroll
    for (int j = 0; j < 4; j++) {
        int t = tid * 4 + j;
        int e = g_topidx[t];
        myexp[j] = e;
        c[e]++;
    }
    // warp inclusive scan
    int inc[NE];
#pragma unroll
    for (int e = 0; e < NE; e++) inc[e] = c[e];
#pragma unroll
    for (int off = 1; off < 32; off <<= 1) {
#pragma unroll
        for (int e = 0; e < NE; e++) {
            int v = __shfl_up_sync(0xffffffffu, inc[e], off);
            if (lane >= off) inc[e] += v;
        }
    }
    if (lane == 31) {
#pragma unroll
        for (int e = 0; e < NE; e++) wtot[warp][e] = inc[e];
    }
    __syncthreads();
    if (warp == 0) {
        int v[NE];
#pragma unroll
        for (int e = 0; e < NE; e++) v[e] = wtot[lane][e];
#pragma unroll
        for (int off = 1; off < 32; off <<= 1) {
#pragma unroll
            for (int e = 0; e < NE; e++) {
                int u = __shfl_up_sync(0xffffffffu, v[e], off);
                if (lane >= off) v[e] += u;
            }
        }
#pragma unroll
        for (int e = 0; e < NE; e++) wtot[lane][e] = v[e];
    }
    __syncthreads();

    int total[NE], run[NE];
#pragma unroll
    for (int e = 0; e < NE; e++) {
        total[e] = wtot[31][e];
        run[e]   = (warp ? wtot[warp - 1][e] : 0) + inc[e] - c[e];  // exclusive prefix
    }
#pragma unroll
    for (int j = 0; j < 4; j++) {
        int t = tid * 4 + j;
        int e = myexp[j];
        run[e]++;
        int pos  = run[e];
        int keep = (pos <= CAP);
        g_kept[t] = keep;
        if (keep) g_tokens[e * CAP + pos - 1] = t;
    }
    if (tid < NE) g_m[tid] = (total[tid] < CAP) ? total[tid] : CAP;

    // aux loss prob sums
    float s[NE];
#pragma unroll
    for (int e = 0; e < NE; e++) s[e] = 0.0f;
#pragma unroll
    for (int j = 0; j < 4; j++) {
        const float4* p4 = reinterpret_cast<const float4*>(g_probs + (size_t)(tid * 4 + j) * NE);
        float4 a = p4[0], bb = p4[1];
        s[0] += a.x; s[1] += a.y; s[2] += a.z; s[3] += a.w;
        s[4] += bb.x; s[5] += bb.y; s[6] += bb.z; s[7] += bb.w;
    }
#pragma unroll
    for (int off = 16; off; off >>= 1)
#pragma unroll
        for (int e = 0; e < NE; e++) s[e] += __shfl_xor_sync(0xffffffffu, s[e], off);
    if (lane == 0) {
#pragma unroll
        for (int e = 0; e < NE; e++) wsum[warp][e] = s[e];
    }
    __syncthreads();
    if (warp == 0) {
        float r[NE];
#pragma unroll
        for (int e = 0; e < NE; e++) r[e] = wsum[lane][e];
#pragma unroll
        for (int off = 16; off; off >>= 1)
#pragma unroll
            for (int e = 0; e < NE; e++) r[e] += __shfl_xor_sync(0xffffffffu, r[e], off);
        if (lane == 0 && aux_out != nullptr) {
            float aux = 0.0f;
            const float invT = 1.0f / (float)T_TOK;
#pragma unroll
            for (int e = 0; e < NE; e++)
                aux += ((float)total[e] * invT) * (r[e] * invT);
            *aux_out = (float)NE * aux;
        }
    }
}

// ---------------- zero only dropped rows -------------------------
__global__ void zero_dropped_kernel(float* __restrict__ out) {
    int t = blockIdx.x;
    if (g_kept[t]) return;
    float4 z = make_float4(0.f, 0.f, 0.f, 0.f);
    reinterpret_cast<float4*>(out + (size_t)t * DIM)[threadIdx.x] = z;
}

// ---------------- HMMA gathered expert GEMM ----------------------
// block 128x64x32, 8 warps (4 M x 2 N), warp tile 32x32.
// acc = Ahi*B + Alo*B  (fp16 split-2 on A, fp32 accum)
#define GBM 128
#define GBN 64
#define GBK 32
#define NITER (DIM / GBK)          // 32
#define ATILE 8192                 // 128 rows x 32 fp16
#define BTILE 4096                 // 64 rows x 32 fp16
#define STAGE_BYTES (2 * ATILE + BTILE)   // 20480
#define SMEM_DATA0 1024
#define SMEM_GEMM (SMEM_DATA0 + 2 * STAGE_BYTES)   // 41984

__device__ __forceinline__ uint32_t sw_off(int row, int kb) {
    return (uint32_t)(row * 64 + ((kb ^ ((row >> 1) & 3)) << 4));
}

__global__ void __launch_bounds__(256, 2) moe_hmma_kernel(
        const float* __restrict__ bias, float* __restrict__ out) {
    int e    = blockIdx.z;
    int m    = g_m[e];
    int row0 = blockIdx.y * GBM;
    if (row0 >= m) return;
    int col0 = blockIdx.x * GBN;

    extern __shared__ char smem[];
    uint32_t sb = smem_u32(smem);
    int tid  = threadIdx.x;
    int wid  = tid >> 5;
    int lane = tid & 31;
    int warp_m = wid & 3;       // 0..3 -> m offset *32
    int warp_n = wid >> 2;      // 0..1 -> n offset *32

    int*   stok  = reinterpret_cast<int*>(smem);          // [128]
    float* sprob = reinterpret_cast<float*>(smem + 512);  // [128]

    if (tid < GBM) {
        int gr  = row0 + tid;
        int tok = (gr < m) ? g_tokens[e * CAP + gr] : 0;
        stok[tid]  = tok;
        sprob[tid] = (gr < m) ? g_topprob[tok] : 0.0f;
    }
    __syncthreads();

    const __half* wt = g_wt + ((size_t)e * DIM + col0) * DIM;

    // loader: A rows tid/4 and tid/4+64, k-chunk tid%4; B row tid/4
    int r0 = tid >> 2, k0 = tid & 3;
    uint32_t d0 = sw_off(r0, k0);
    uint32_t d1 = sw_off(r0 + 64, k0);
    size_t a0row = (size_t)stok[r0] * DIM;
    size_t a1row = (size_t)stok[r0 + 64] * DIM;
    size_t brow  = (size_t)r0 * DIM;

#define ISSUE_STAGE(S, KC0)                                                   \
    do {                                                                      \
        uint32_t st = sb + SMEM_DATA0 + (uint32_t)(S) * STAGE_BYTES;          \
        int ka = (KC0) + k0 * 8;                                              \
        cpasync16(st + d0,             g_xhi + a0row + ka);                   \
        cpasync16(st + d1,             g_xhi + a1row + ka);                   \
        cpasync16(st + ATILE + d0,     g_xlo + a0row + ka);                   \
        cpasync16(st + ATILE + d1,     g_xlo + a1row + ka);                   \
        cpasync16(st + 2 * ATILE + d0, wt + brow + ka);                       \
        cp_commit();                                                          \
    } while (0)

    // ldmatrix lane offsets
    int q = lane >> 3, r = lane & 7;
    uint32_t a_off[2][2], b_off[2][2];
#pragma unroll
    for (int mt = 0; mt < 2; mt++)
#pragma unroll
        for (int ks = 0; ks < 2; ks++) {
            int mm = warp_m * 32 + mt * 16 + (q & 1) * 8 + r;
            int kb = ks * 2 + (q >> 1);
            a_off[mt][ks] = sw_off(mm, kb);
        }
#pragma unroll
    for (int nt2 = 0; nt2 < 2; nt2++)
#pragma unroll
        for (int ks = 0; ks < 2; ks++) {
            int nn = warp_n * 32 + nt2 * 16 + (q & 1) * 8 + r;
            int kb = ks * 2 + (q >> 1);
            b_off[nt2][ks] = sw_off(nn, kb);
        }

    float acc[2][4][4];
#pragma unroll
    for (int mt = 0; mt < 2; mt++)
#pragma unroll
        for (int nt = 0; nt < 4; nt++)
#pragma unroll
            for (int j = 0; j < 4; j++) acc[mt][nt][j] = 0.0f;

    ISSUE_STAGE(0, 0);

    for (int c = 0; c < NITER; c++) {
        cp_wait_all();
        __syncthreads();
        if (c + 1 < NITER) ISSUE_STAGE((c + 1) & 1, (c + 1) * GBK);

        uint32_t st = sb + SMEM_DATA0 + (uint32_t)(c & 1) * STAGE_BYTES;
#pragma unroll
        for (int ks = 0; ks < 2; ks++) {
            uint32_t ah[2][4], al[2][4];
#pragma unroll
            for (int mt = 0; mt < 2; mt++) {
                LDSM4(ah[mt][0], ah[mt][1], ah[mt][2], ah[mt][3], st + a_off[mt][ks]);
                LDSM4(al[mt][0], al[mt][1], al[mt][2], al[mt][3], st + ATILE + a_off[mt][ks]);
            }
            uint32_t b[4][2];
#pragma unroll
            for (int nt2 = 0; nt2 < 2; nt2++) {
                uint32_t t0, t1, t2, t3;
                LDSM4(t0, t1, t2, t3, st + 2 * ATILE + b_off[nt2][ks]);
                b[nt2 * 2][0] = t0; b[nt2 * 2][1] = t2;
                b[nt2 * 2 + 1][0] = t1; b[nt2 * 2 + 1][1] = t3;
            }
#pragma unroll
            for (int mt = 0; mt < 2; mt++)
#pragma unroll
                for (int nt = 0; nt < 4; nt++)
                    MMA16816(acc[mt][nt], ah[mt], b[nt][0], b[nt][1]);
#pragma unroll
            for (int mt = 0; mt < 2; mt++)
#pragma unroll
                for (int nt = 0; nt < 4; nt++)
                    MMA16816(acc[mt][nt], al[mt], b[nt][0], b[nt][1]);
        }
        __syncthreads();
    }

    // epilogue: scatter with bias + prob scale
    int tq = lane >> 2;          // row within 8
    int tr = lane & 3;           // col pair
    const float* be = bias + (size_t)e * DIM;
#pragma unroll
    for (int nt = 0; nt < 4; nt++) {
        int col = col0 + warp_n * 32 + nt * 8 + tr * 2;
        float2 bb = *reinterpret_cast<const float2*>(be + col);
#pragma unroll
        for (int mt = 0; mt < 2; mt++) {
#pragma unroll
            for (int h = 0; h < 2; h++) {
                int rw = warp_m * 32 + mt * 16 + h * 8 + tq;
                int gr = row0 + rw;
                if (gr < m) {
                    int   tok = stok[rw];
                    float p   = sprob[rw];
                    float2 o;
                    o.x = (acc[mt][nt][h * 2 + 0] + bb.x) * p;
                    o.y = (acc[mt][nt][h * 2 + 1] + bb.y) * p;
                    *reinterpret_cast<float2*>(out + (size_t)tok * DIM + col) = o;
                }
            }
        }
    }
}

// ---------------- launch ----------------
extern "C" void kernel_launch(void* const* d_in, const int* in_sizes, int n_in,
                              void* d_out, int out_size) {
    const float* x  = (const float*)d_in[0];   // [T, D]
    const float* Wg = (const float*)d_in[1];   // [D, E]
    const float* bg = (const float*)d_in[2];   // [E]
    const float* W  = (const float*)d_in[3];   // [E, D, D]
    const float* b  = (const float*)d_in[4];   // [E, D]
    float* out = (float*)d_out;

    // gating + x fp16 split (reads x once)
    gating_split_kernel<<<(T_TOK * 32 + 255) / 256, 256>>>(x, Wg, bg);

    // W^T fp16
    {
        dim3 grid(DIM / 32, DIM / 32, NE);
        dim3 blk(32, 8);
        convert_w_kernel<<<grid, blk>>>(W);
    }

    // routing scan + aux loss
    float* aux_out = (out_size > T_TOK * DIM) ? (out + (size_t)T_TOK * DIM) : nullptr;
    route_kernel<<<1, 1024>>>(aux_out);

    // zero only dropped token rows (output poisoned by harness)
    zero_dropped_kernel<<<T_TOK, 256>>>(out);

    // HMMA gathered expert GEMM
    cudaFuncSetAttribute(moe_hmma_kernel,
                         cudaFuncAttributeMaxDynamicSharedMemorySize, SMEM_GEMM);
    dim3 grid(DIM / GBN, (CAP + GBM - 1) / GBM, NE);
    moe_hmma_kernel<<<grid, 256, SMEM_GEMM>>>(b, out);
}

// round 5
// speedup vs baseline: 2.7846x; 1.2209x over previous
#include <cuda_runtime.h>
#include <cuda_fp16.h>
#include <cstdint>

#define T_TOK 4096
#define DIM   1024
#define NE    8
#define CAP   640   // int(1.25 * 4096 / 8)

// ---------------- scratch (no cudaMalloc allowed) ----------------
__device__ int   g_topidx[T_TOK];
__device__ float g_topprob[T_TOK];
__device__ float g_probs[T_TOK * NE];
__device__ int   g_tokens[NE * CAP];
__device__ int   g_m[NE];
__device__ int   g_kept[T_TOK];

// fp16 operands: x split hi/lo, W^T single fp16
__device__ __half g_xhi[T_TOK * DIM];        // 8 MB
__device__ __half g_xlo[T_TOK * DIM];        // 8 MB
__device__ __half g_wt[NE * DIM * DIM];      // 16 MB  W^T : [e][n][k]

// ---------------- helpers ----------------
__device__ __forceinline__ uint32_t smem_u32(const void* p) {
    uint32_t a;
    asm("{ .reg .u64 t; cvta.to.shared.u64 t, %1; cvt.u32.u64 %0, t; }" : "=r"(a) : "l"(p));
    return a;
}
__device__ __forceinline__ void cpasync16(uint32_t dst, const void* src) {
    asm volatile("cp.async.cg.shared.global [%0], [%1], 16;"
                 :: "r"(dst), "l"(__cvta_generic_to_global(src)) : "memory");
}
__device__ __forceinline__ void cp_commit() {
    asm volatile("cp.async.commit_group;" ::: "memory");
}
__device__ __forceinline__ void cp_wait1() {
    asm volatile("cp.async.wait_group 1;" ::: "memory");
}
#define LDSM4(r0, r1, r2, r3, a)                                             \
    asm volatile("ldmatrix.sync.aligned.m8n8.x4.shared.b16 {%0,%1,%2,%3}, [%4];" \
                 : "=r"(r0), "=r"(r1), "=r"(r2), "=r"(r3) : "r"(a))
#define MMA16816(d, a, b0v, b1v)                                             \
    asm volatile("mma.sync.aligned.m16n8k16.row.col.f32.f16.f16.f32 "        \
                 "{%0,%1,%2,%3},{%4,%5,%6,%7},{%8,%9},{%0,%1,%2,%3};"        \
                 : "+f"((d)[0]), "+f"((d)[1]), "+f"((d)[2]), "+f"((d)[3])    \
                 : "r"((a)[0]), "r"((a)[1]), "r"((a)[2]), "r"((a)[3]),       \
                   "r"(b0v), "r"(b1v))

// ---------------- fused gating + x split (one warp / 2 tokens) ---
__global__ void gating_split_kernel(const float* __restrict__ x,
                                    const float* __restrict__ Wg,
                                    const float* __restrict__ bg) {
    int warp = (blockIdx.x * blockDim.x + threadIdx.x) >> 5;
    int lane = threadIdx.x & 31;
    if (warp >= T_TOK / 2) return;
    int t0 = warp * 2, t1 = warp * 2 + 1;

    const float4* x0 = reinterpret_cast<const float4*>(x + (size_t)t0 * DIM);
    const float4* x1 = reinterpret_cast<const float4*>(x + (size_t)t1 * DIM);
    float a0[NE], a1[NE];
#pragma unroll
    for (int e = 0; e < NE; e++) { a0[e] = 0.0f; a1[e] = 0.0f; }

#pragma unroll
    for (int j = 0; j < 8; j++) {
        int d = j * 128 + lane * 4;
        float4 v0 = x0[d >> 2];
        float4 v1 = x1[d >> 2];
        float f0[4] = {v0.x, v0.y, v0.z, v0.w};
        float f1[4] = {v1.x, v1.y, v1.z, v1.w};
        __half h0[4], l0[4], h1[4], l1[4];
#pragma unroll
        for (int i = 0; i < 4; i++) {
            h0[i] = __float2half(f0[i]);
            l0[i] = __float2half(f0[i] - __half2float(h0[i]));
            h1[i] = __float2half(f1[i]);
            l1[i] = __float2half(f1[i] - __half2float(h1[i]));
            const float4* wg4 = reinterpret_cast<const float4*>(Wg + (size_t)(d + i) * NE);
            float4 w0 = wg4[0];
            float4 w1 = wg4[1];
            a0[0] += f0[i] * w0.x; a0[1] += f0[i] * w0.y;
            a0[2] += f0[i] * w0.z; a0[3] += f0[i] * w0.w;
            a0[4] += f0[i] * w1.x; a0[5] += f0[i] * w1.y;
            a0[6] += f0[i] * w1.z; a0[7] += f0[i] * w1.w;
            a1[0] += f1[i] * w0.x; a1[1] += f1[i] * w0.y;
            a1[2] += f1[i] * w0.z; a1[3] += f1[i] * w0.w;
            a1[4] += f1[i] * w1.x; a1[5] += f1[i] * w1.y;
            a1[6] += f1[i] * w1.z; a1[7] += f1[i] * w1.w;
        }
        size_t o0 = (size_t)t0 * DIM + d;
        size_t o1 = (size_t)t1 * DIM + d;
        *reinterpret_cast<uint2*>(g_xhi + o0) = *reinterpret_cast<uint2*>(h0);
        *reinterpret_cast<uint2*>(g_xlo + o0) = *reinterpret_cast<uint2*>(l0);
        *reinterpret_cast<uint2*>(g_xhi + o1) = *reinterpret_cast<uint2*>(h1);
        *reinterpret_cast<uint2*>(g_xlo + o1) = *reinterpret_cast<uint2*>(l1);
    }
#pragma unroll
    for (int e = 0; e < NE; e++) {
#pragma unroll
        for (int off = 16; off; off >>= 1) {
            a0[e] += __shfl_xor_sync(0xffffffffu, a0[e], off);
            a1[e] += __shfl_xor_sync(0xffffffffu, a1[e], off);
        }
    }

    if (lane == 0) {
#pragma unroll
        for (int tt = 0; tt < 2; tt++) {
            float* acc = tt ? a1 : a0;
            int t = tt ? t1 : t0;
            float l[NE], p[NE];
            float mx = -1e30f;
            int arg = 0;
#pragma unroll
            for (int e = 0; e < NE; e++) l[e] = acc[e] + bg[e];
#pragma unroll
            for (int e = 0; e < NE; e++) {
                if (l[e] > mx) { mx = l[e]; arg = e; }
            }
            float s = 0.0f;
#pragma unroll
            for (int e = 0; e < NE; e++) { p[e] = expf(l[e] - mx); s += p[e]; }
            float inv = 1.0f / s;
#pragma unroll
            for (int e = 0; e < NE; e++) g_probs[(size_t)t * NE + e] = p[e] * inv;
            g_topidx[t]  = arg;
            g_topprob[t] = p[arg] * inv;
        }
    }
}

// ---------------- W transpose + fp16 convert ---------------------
__global__ void convert_w_kernel(const float* __restrict__ W) {
    __shared__ float t[32][33];
    int e  = blockIdx.z;
    int kb = blockIdx.y * 32;
    int nb = blockIdx.x * 32;
    int tx = threadIdx.x, ty = threadIdx.y;   // block (32, 8)
    const float* we = W + (size_t)e * DIM * DIM;
#pragma unroll
    for (int j = 0; j < 32; j += 8)
        t[ty + j][tx] = we[(size_t)(kb + ty + j) * DIM + nb + tx];
    __syncthreads();
#pragma unroll
    for (int j = 0; j < 32; j += 8) {
        int n = nb + ty + j;
        int k = kb + tx;
        g_wt[(size_t)e * DIM * DIM + (size_t)n * DIM + k] = __float2half(t[tx][ty + j]);
    }
}

// ---------------- routing scan (shfl-based) ----------------------
__global__ void __launch_bounds__(1024) route_kernel(float* __restrict__ aux_out) {
    __shared__ int   wtot[32][NE];
    __shared__ float wsum[32][NE];
    int tid  = threadIdx.x;
    int lane = tid & 31;
    int warp = tid >> 5;

    int c[NE];
#pragma unroll
    for (int e = 0; e < NE; e++) c[e] = 0;
    int myexp[4];
#pragma unroll
    for (int j = 0; j < 4; j++) {
        int t = tid * 4 + j;
        int e = g_topidx[t];
        myexp[j] = e;
        c[e]++;
    }
    int inc[NE];
#pragma unroll
    for (int e = 0; e < NE; e++) inc[e] = c[e];
#pragma unroll
    for (int off = 1; off < 32; off <<= 1) {
#pragma unroll
        for (int e = 0; e < NE; e++) {
            int v = __shfl_up_sync(0xffffffffu, inc[e], off);
            if (lane >= off) inc[e] += v;
        }
    }
    if (lane == 31) {
#pragma unroll
        for (int e = 0; e < NE; e++) wtot[warp][e] = inc[e];
    }
    __syncthreads();
    if (warp == 0) {
        int v[NE];
#pragma unroll
        for (int e = 0; e < NE; e++) v[e] = wtot[lane][e];
#pragma unroll
        for (int off = 1; off < 32; off <<= 1) {
#pragma unroll
            for (int e = 0; e < NE; e++) {
                int u = __shfl_up_sync(0xffffffffu, v[e], off);
                if (lane >= off) v[e] += u;
            }
        }
#pragma unroll
        for (int e = 0; e < NE; e++) wtot[lane][e] = v[e];
    }
    __syncthreads();

    int total[NE], run[NE];
#pragma unroll
    for (int e = 0; e < NE; e++) {
        total[e] = wtot[31][e];
        run[e]   = (warp ? wtot[warp - 1][e] : 0) + inc[e] - c[e];
    }
#pragma unroll
    for (int j = 0; j < 4; j++) {
        int t = tid * 4 + j;
        int e = myexp[j];
        run[e]++;
        int pos  = run[e];
        int keep = (pos <= CAP);
        g_kept[t] = keep;
        if (keep) g_tokens[e * CAP + pos - 1] = t;
    }
    if (tid < NE) g_m[tid] = (total[tid] < CAP) ? total[tid] : CAP;

    float s[NE];
#pragma unroll
    for (int e = 0; e < NE; e++) s[e] = 0.0f;
#pragma unroll
    for (int j = 0; j < 4; j++) {
        const float4* p4 = reinterpret_cast<const float4*>(g_probs + (size_t)(tid * 4 + j) * NE);
        float4 a = p4[0], bb = p4[1];
        s[0] += a.x; s[1] += a.y; s[2] += a.z; s[3] += a.w;
        s[4] += bb.x; s[5] += bb.y; s[6] += bb.z; s[7] += bb.w;
    }
#pragma unroll
    for (int off = 16; off; off >>= 1)
#pragma unroll
        for (int e = 0; e < NE; e++) s[e] += __shfl_xor_sync(0xffffffffu, s[e], off);
    if (lane == 0) {
#pragma unroll
        for (int e = 0; e < NE; e++) wsum[warp][e] = s[e];
    }
    __syncthreads();
    if (warp == 0) {
        float r[NE];
#pragma unroll
        for (int e = 0; e < NE; e++) r[e] = wsum[lane][e];
#pragma unroll
        for (int off = 16; off; off >>= 1)
#pragma unroll
            for (int e = 0; e < NE; e++) r[e] += __shfl_xor_sync(0xffffffffu, r[e], off);
        if (lane == 0 && aux_out != nullptr) {
            float aux = 0.0f;
            const float invT = 1.0f / (float)T_TOK;
#pragma unroll
            for (int e = 0; e < NE; e++)
                aux += ((float)total[e] * invT) * (r[e] * invT);
            *aux_out = (float)NE * aux;
        }
    }
}

// ---------------- zero only dropped rows (16 tok / block) --------
__global__ void zero_dropped_kernel(float* __restrict__ out) {
    int base = blockIdx.x * 16;
    float4 z = make_float4(0.f, 0.f, 0.f, 0.f);
#pragma unroll
    for (int j = 0; j < 16; j++) {
        int t = base + j;
        if (!g_kept[t])
            reinterpret_cast<float4*>(out + (size_t)t * DIM)[threadIdx.x] = z;
    }
}

// ---------------- HMMA gathered expert GEMM ----------------------
// block 128x128x32, 8 warps (4 M x 2 N), warp tile 32x64, 3-stage pipe.
// acc = Ahi*B + Alo*B  (fp16 split-2 on A, fp32 accum)
#define GBM 128
#define GBN 128
#define GBK 32
#define NITER (DIM / GBK)          // 32
#define ATILE 8192                 // 128 rows x 32 fp16
#define BTILE 8192                 // 128 rows x 32 fp16
#define STAGE_BYTES (2 * ATILE + BTILE)   // 24576
#define NSTAGE 3
#define SMEM_DATA0 1024
#define SMEM_GEMM (SMEM_DATA0 + NSTAGE * STAGE_BYTES)   // 74752

__device__ __forceinline__ uint32_t sw_off(int row, int kb) {
    return (uint32_t)(row * 64 + ((kb ^ ((row >> 1) & 3)) << 4));
}

__global__ void __launch_bounds__(256, 2) moe_hmma_kernel(
        const float* __restrict__ bias, float* __restrict__ out) {
    int e    = blockIdx.z;
    int m    = g_m[e];
    int row0 = blockIdx.y * GBM;
    if (row0 >= m) return;
    int col0 = blockIdx.x * GBN;

    extern __shared__ char smem[];
    uint32_t sb = smem_u32(smem);
    int tid  = threadIdx.x;
    int wid  = tid >> 5;
    int lane = tid & 31;
    int warp_m = wid & 3;       // 0..3 -> m offset *32
    int warp_n = wid >> 2;      // 0..1 -> n offset *64

    int*   stok  = reinterpret_cast<int*>(smem);          // [128]
    float* sprob = reinterpret_cast<float*>(smem + 512);  // [128]

    if (tid < GBM) {
        int gr  = row0 + tid;
        int tok = (gr < m) ? g_tokens[e * CAP + gr] : 0;
        stok[tid]  = tok;
        sprob[tid] = (gr < m) ? g_topprob[tok] : 0.0f;
    }
    __syncthreads();

    const __half* wt = g_wt + ((size_t)e * DIM + col0) * DIM;

    // loader: rows tid/4 and tid/4+64, k-chunk tid%4 (A hi/lo + B)
    int r0 = tid >> 2, k0 = tid & 3;
    uint32_t d0 = sw_off(r0, k0);
    uint32_t d1 = sw_off(r0 + 64, k0);
    size_t a0row = (size_t)stok[r0] * DIM;
    size_t a1row = (size_t)stok[r0 + 64] * DIM;
    size_t b0row = (size_t)r0 * DIM;
    size_t b1row = (size_t)(r0 + 64) * DIM;

#define ISSUE_STAGE(S, KC0)                                                   \
    do {                                                                      \
        uint32_t st = sb + SMEM_DATA0 + (uint32_t)(S) * STAGE_BYTES;          \
        int ka = (KC0) + k0 * 8;                                              \
        cpasync16(st + d0,             g_xhi + a0row + ka);                   \
        cpasync16(st + d1,             g_xhi + a1row + ka);                   \
        cpasync16(st + ATILE + d0,     g_xlo + a0row + ka);                   \
        cpasync16(st + ATILE + d1,     g_xlo + a1row + ka);                   \
        cpasync16(st + 2 * ATILE + d0, wt + b0row + ka);                      \
        cpasync16(st + 2 * ATILE + d1, wt + b1row + ka);                      \
        cp_commit();                                                          \
    } while (0)

    // ldmatrix lane offsets
    int q = lane >> 3, r = lane & 7;
    uint32_t a_off[2][2], b_off[4][2];
#pragma unroll
    for (int mt = 0; mt < 2; mt++)
#pragma unroll
        for (int ks = 0; ks < 2; ks++) {
            int mm = warp_m * 32 + mt * 16 + (q & 1) * 8 + r;
            int kb = ks * 2 + (q >> 1);
            a_off[mt][ks] = sw_off(mm, kb);
        }
#pragma unroll
    for (int nt2 = 0; nt2 < 4; nt2++)
#pragma unroll
        for (int ks = 0; ks < 2; ks++) {
            int nn = warp_n * 64 + nt2 * 16 + (q & 1) * 8 + r;
            int kb = ks * 2 + (q >> 1);
            b_off[nt2][ks] = sw_off(nn, kb);
        }

    float acc[2][8][4];
#pragma unroll
    for (int mt = 0; mt < 2; mt++)
#pragma unroll
        for (int nt = 0; nt < 8; nt++)
#pragma unroll
            for (int j = 0; j < 4; j++) acc[mt][nt][j] = 0.0f;

    ISSUE_STAGE(0, 0);
    ISSUE_STAGE(1, GBK);

    int stage = 0;
    for (int c = 0; c < NITER; c++) {
        cp_wait1();            // stage c complete (c+1 may still be in flight)
        __syncthreads();
        if (c + 2 < NITER) {
            int s2 = stage + 2;
            if (s2 >= NSTAGE) s2 -= NSTAGE;
            ISSUE_STAGE(s2, (c + 2) * GBK);
        }

        uint32_t st = sb + SMEM_DATA0 + (uint32_t)stage * STAGE_BYTES;
#pragma unroll
        for (int ks = 0; ks < 2; ks++) {
            uint32_t ah[2][4], al[2][4];
#pragma unroll
            for (int mt = 0; mt < 2; mt++) {
                LDSM4(ah[mt][0], ah[mt][1], ah[mt][2], ah[mt][3], st + a_off[mt][ks]);
                LDSM4(al[mt][0], al[mt][1], al[mt][2], al[mt][3], st + ATILE + a_off[mt][ks]);
            }
#pragma unroll
            for (int nt2 = 0; nt2 < 4; nt2++) {
                uint32_t t0, t1, t2, t3;
                LDSM4(t0, t1, t2, t3, st + 2 * ATILE + b_off[nt2][ks]);
#pragma unroll
                for (int mt = 0; mt < 2; mt++) {
                    MMA16816(acc[mt][nt2 * 2],     ah[mt], t0, t2);
                    MMA16816(acc[mt][nt2 * 2 + 1], ah[mt], t1, t3);
                    MMA16816(acc[mt][nt2 * 2],     al[mt], t0, t2);
                    MMA16816(acc[mt][nt2 * 2 + 1], al[mt], t1, t3);
                }
            }
        }
        stage++;
        if (stage >= NSTAGE) stage -= NSTAGE;
    }

    // epilogue: scatter with bias + prob scale
    int tq = lane >> 2;          // row within 8
    int tr = lane & 3;           // col pair
    const float* be = bias + (size_t)e * DIM;
#pragma unroll
    for (int nt = 0; nt < 8; nt++) {
        int col = col0 + warp_n * 64 + nt * 8 + tr * 2;
        float2 bb = *reinterpret_cast<const float2*>(be + col);
#pragma unroll
        for (int mt = 0; mt < 2; mt++) {
#pragma unroll
            for (int h = 0; h < 2; h++) {
                int rw = warp_m * 32 + mt * 16 + h * 8 + tq;
                int gr = row0 + rw;
                if (gr < m) {
                    int   tok = stok[rw];
                    float p   = sprob[rw];
                    float2 o;
                    o.x = (acc[mt][nt][h * 2 + 0] + bb.x) * p;
                    o.y = (acc[mt][nt][h * 2 + 1] + bb.y) * p;
                    *reinterpret_cast<float2*>(out + (size_t)tok * DIM + col) = o;
                }
            }
        }
    }
}

// ---------------- launch ----------------
extern "C" void kernel_launch(void* const* d_in, const int* in_sizes, int n_in,
                              void* d_out, int out_size) {
    const float* x  = (const float*)d_in[0];   // [T, D]
    const float* Wg = (const float*)d_in[1];   // [D, E]
    const float* bg = (const float*)d_in[2];   // [E]
    const float* W  = (const float*)d_in[3];   // [E, D, D]
    const float* b  = (const float*)d_in[4];   // [E, D]
    float* out = (float*)d_out;

    // gating + x fp16 split (2 tokens per warp)
    gating_split_kernel<<<T_TOK / 2 * 32 / 256, 256>>>(x, Wg, bg);

    // W^T fp16
    {
        dim3 grid(DIM / 32, DIM / 32, NE);
        dim3 blk(32, 8);
        convert_w_kernel<<<grid, blk>>>(W);
    }

    // routing scan + aux loss
    float* aux_out = (out_size > T_TOK * DIM) ? (out + (size_t)T_TOK * DIM) : nullptr;
    route_kernel<<<1, 1024>>>(aux_out);

    // zero only dropped token rows
    zero_dropped_kernel<<<T_TOK / 16, 256>>>(out);

    // HMMA gathered expert GEMM
    cudaFuncSetAttribute(moe_hmma_kernel,
                         cudaFuncAttributeMaxDynamicSharedMemorySize, SMEM_GEMM);
    dim3 grid(DIM / GBN, (CAP + GBM - 1) / GBM, NE);
    moe_hmma_kernel<<<grid, 256, SMEM_GEMM>>>(b, out);
}

// round 6
// speedup vs baseline: 3.1237x; 1.1218x over previous
#include <cuda_runtime.h>
#include <cuda_fp16.h>
#include <cstdint>

#define T_TOK 4096
#define DIM   1024
#define NE    8
#define CAP   640   // int(1.25 * 4096 / 8)

// ---------------- scratch (no cudaMalloc allowed) ----------------
__device__ int   g_topidx[T_TOK];
__device__ float g_topprob[T_TOK];
__device__ float g_probs[T_TOK * NE];
__device__ int   g_tokens[NE * CAP];
__device__ int   g_m[NE];

// fp16 operands
__device__ __half g_xh[T_TOK * DIM];         // 8 MB
__device__ __half g_wt[NE * DIM * DIM];      // 16 MB  W^T : [e][n][k]

// ---------------- helpers ----------------
__device__ __forceinline__ uint32_t smem_u32(const void* p) {
    uint32_t a;
    asm("{ .reg .u64 t; cvta.to.shared.u64 t, %1; cvt.u32.u64 %0, t; }" : "=r"(a) : "l"(p));
    return a;
}
__device__ __forceinline__ void cpasync16(uint32_t dst, const void* src) {
    asm volatile("cp.async.cg.shared.global [%0], [%1], 16;"
                 :: "r"(dst), "l"(__cvta_generic_to_global(src)) : "memory");
}
__device__ __forceinline__ void cp_commit() {
    asm volatile("cp.async.commit_group;" ::: "memory");
}
__device__ __forceinline__ void cp_wait2() {
    asm volatile("cp.async.wait_group 2;" ::: "memory");
}
#define LDSM4(r0, r1, r2, r3, a)                                             \
    asm volatile("ldmatrix.sync.aligned.m8n8.x4.shared.b16 {%0,%1,%2,%3}, [%4];" \
                 : "=r"(r0), "=r"(r1), "=r"(r2), "=r"(r3) : "r"(a))
#define MMA16816(d, a, b0v, b1v)                                             \
    asm volatile("mma.sync.aligned.m16n8k16.row.col.f32.f16.f16.f32 "        \
                 "{%0,%1,%2,%3},{%4,%5,%6,%7},{%8,%9},{%0,%1,%2,%3};"        \
                 : "+f"((d)[0]), "+f"((d)[1]), "+f"((d)[2]), "+f"((d)[3])    \
                 : "r"((a)[0]), "r"((a)[1]), "r"((a)[2]), "r"((a)[3]),       \
                   "r"(b0v), "r"(b1v))

// ================= prep kernel: convert_w + gating + zero ========
// blocks [0, 8192)        : W transpose + fp16 convert
// blocks [8192, 8448)     : gating + x fp16 convert (2 tok / warp)
// blocks [8448, 9472)     : zero out[16MB]
#define PREP_WBLKS 8192
#define PREP_GBLKS 256
#define PREP_ZBLKS 1024
#define PREP_BLOCKS (PREP_WBLKS + PREP_GBLKS + PREP_ZBLKS)

__global__ void __launch_bounds__(256) prep_kernel(
        const float* __restrict__ x,  const float* __restrict__ Wg,
        const float* __restrict__ bg, const float* __restrict__ W,
        float* __restrict__ out) {
    int bid = blockIdx.x;
    int tid = threadIdx.x;

    if (bid < PREP_WBLKS) {
        // ---- W[e][k][n] -> g_wt[e][n][k] fp16 ----
        __shared__ float t[32][33];
        int e   = bid >> 10;
        int rem = bid & 1023;
        int nb  = (rem & 31) * 32;
        int kb  = (rem >> 5) * 32;
        int tx = tid & 31, ty = tid >> 5;   // (32, 8)
        const float* we = W + (size_t)e * DIM * DIM;
#pragma unroll
        for (int j = 0; j < 32; j += 8)
            t[ty + j][tx] = we[(size_t)(kb + ty + j) * DIM + nb + tx];
        __syncthreads();
#pragma unroll
        for (int j = 0; j < 32; j += 8) {
            int n = nb + ty + j;
            int k = kb + tx;
            g_wt[(size_t)e * DIM * DIM + (size_t)n * DIM + k] = __float2half(t[tx][ty + j]);
        }
        return;
    }
    if (bid < PREP_WBLKS + PREP_GBLKS) {
        // ---- gating + x fp16 convert ----
        int warp = (bid - PREP_WBLKS) * 8 + (tid >> 5);
        int lane = tid & 31;
        int t0 = warp * 2, t1 = warp * 2 + 1;

        const float4* x0 = reinterpret_cast<const float4*>(x + (size_t)t0 * DIM);
        const float4* x1 = reinterpret_cast<const float4*>(x + (size_t)t1 * DIM);
        float a0[NE], a1[NE];
#pragma unroll
        for (int e = 0; e < NE; e++) { a0[e] = 0.0f; a1[e] = 0.0f; }

#pragma unroll
        for (int j = 0; j < 8; j++) {
            int d = j * 128 + lane * 4;
            float4 v0 = x0[d >> 2];
            float4 v1 = x1[d >> 2];
            float f0[4] = {v0.x, v0.y, v0.z, v0.w};
            float f1[4] = {v1.x, v1.y, v1.z, v1.w};
            __half h0[4], h1[4];
#pragma unroll
            for (int i = 0; i < 4; i++) {
                h0[i] = __float2half(f0[i]);
                h1[i] = __float2half(f1[i]);
                const float4* wg4 = reinterpret_cast<const float4*>(Wg + (size_t)(d + i) * NE);
                float4 w0 = wg4[0];
                float4 w1 = wg4[1];
                a0[0] += f0[i] * w0.x; a0[1] += f0[i] * w0.y;
                a0[2] += f0[i] * w0.z; a0[3] += f0[i] * w0.w;
                a0[4] += f0[i] * w1.x; a0[5] += f0[i] * w1.y;
                a0[6] += f0[i] * w1.z; a0[7] += f0[i] * w1.w;
                a1[0] += f1[i] * w0.x; a1[1] += f1[i] * w0.y;
                a1[2] += f1[i] * w0.z; a1[3] += f1[i] * w0.w;
                a1[4] += f1[i] * w1.x; a1[5] += f1[i] * w1.y;
                a1[6] += f1[i] * w1.z; a1[7] += f1[i] * w1.w;
            }
            *reinterpret_cast<uint2*>(g_xh + (size_t)t0 * DIM + d) = *reinterpret_cast<uint2*>(h0);
            *reinterpret_cast<uint2*>(g_xh + (size_t)t1 * DIM + d) = *reinterpret_cast<uint2*>(h1);
        }
#pragma unroll
        for (int e = 0; e < NE; e++) {
#pragma unroll
            for (int off = 16; off; off >>= 1) {
                a0[e] += __shfl_xor_sync(0xffffffffu, a0[e], off);
                a1[e] += __shfl_xor_sync(0xffffffffu, a1[e], off);
            }
        }
        if (lane == 0) {
#pragma unroll
            for (int tt = 0; tt < 2; tt++) {
                float* acc = tt ? a1 : a0;
                int t = tt ? t1 : t0;
                float l[NE], p[NE];
                float mx = -1e30f;
                int arg = 0;
#pragma unroll
                for (int e = 0; e < NE; e++) l[e] = acc[e] + bg[e];
#pragma unroll
                for (int e = 0; e < NE; e++) {
                    if (l[e] > mx) { mx = l[e]; arg = e; }
                }
                float s = 0.0f;
#pragma unroll
                for (int e = 0; e < NE; e++) { p[e] = expf(l[e] - mx); s += p[e]; }
                float inv = 1.0f / s;
#pragma unroll
                for (int e = 0; e < NE; e++) g_probs[(size_t)t * NE + e] = p[e] * inv;
                g_topidx[t]  = arg;
                g_topprob[t] = p[arg] * inv;
            }
        }
        return;
    }
    // ---- zero out (full 16 MB) ----
    {
        int zb = bid - PREP_WBLKS - PREP_GBLKS;   // 0..1023
        float4 z = make_float4(0.f, 0.f, 0.f, 0.f);
        float4* o4 = reinterpret_cast<float4*>(out) + (size_t)zb * 1024 + tid;
#pragma unroll
        for (int j = 0; j < 4; j++) o4[j * 256] = z;
    }
}

// ---------------- routing scan (shfl-based) ----------------------
__global__ void __launch_bounds__(1024) route_kernel(float* __restrict__ aux_out) {
    __shared__ int   wtot[32][NE];
    __shared__ float wsum[32][NE];
    int tid  = threadIdx.x;
    int lane = tid & 31;
    int warp = tid >> 5;

    int c[NE];
#pragma unroll
    for (int e = 0; e < NE; e++) c[e] = 0;
    int myexp[4];
#pragma unroll
    for (int j = 0; j < 4; j++) {
        int t = tid * 4 + j;
        int e = g_topidx[t];
        myexp[j] = e;
        c[e]++;
    }
    int inc[NE];
#pragma unroll
    for (int e = 0; e < NE; e++) inc[e] = c[e];
#pragma unroll
    for (int off = 1; off < 32; off <<= 1) {
#pragma unroll
        for (int e = 0; e < NE; e++) {
            int v = __shfl_up_sync(0xffffffffu, inc[e], off);
            if (lane >= off) inc[e] += v;
        }
    }
    if (lane == 31) {
#pragma unroll
        for (int e = 0; e < NE; e++) wtot[warp][e] = inc[e];
    }
    __syncthreads();
    if (warp == 0) {
        int v[NE];
#pragma unroll
        for (int e = 0; e < NE; e++) v[e] = wtot[lane][e];
#pragma unroll
        for (int off = 1; off < 32; off <<= 1) {
#pragma unroll
            for (int e = 0; e < NE; e++) {
                int u = __shfl_up_sync(0xffffffffu, v[e], off);
                if (lane >= off) v[e] += u;
            }
        }
#pragma unroll
        for (int e = 0; e < NE; e++) wtot[lane][e] = v[e];
    }
    __syncthreads();

    int total[NE], run[NE];
#pragma unroll
    for (int e = 0; e < NE; e++) {
        total[e] = wtot[31][e];
        run[e]   = (warp ? wtot[warp - 1][e] : 0) + inc[e] - c[e];
    }
#pragma unroll
    for (int j = 0; j < 4; j++) {
        int t = tid * 4 + j;
        int e = myexp[j];
        run[e]++;
        int pos = run[e];
        if (pos <= CAP) g_tokens[e * CAP + pos - 1] = t;
    }
    if (tid < NE) g_m[tid] = (total[tid] < CAP) ? total[tid] : CAP;

    float s[NE];
#pragma unroll
    for (int e = 0; e < NE; e++) s[e] = 0.0f;
#pragma unroll
    for (int j = 0; j < 4; j++) {
        const float4* p4 = reinterpret_cast<const float4*>(g_probs + (size_t)(tid * 4 + j) * NE);
        float4 a = p4[0], bb = p4[1];
        s[0] += a.x; s[1] += a.y; s[2] += a.z; s[3] += a.w;
        s[4] += bb.x; s[5] += bb.y; s[6] += bb.z; s[7] += bb.w;
    }
#pragma unroll
    for (int off = 16; off; off >>= 1)
#pragma unroll
        for (int e = 0; e < NE; e++) s[e] += __shfl_xor_sync(0xffffffffu, s[e], off);
    if (lane == 0) {
#pragma unroll
        for (int e = 0; e < NE; e++) wsum[warp][e] = s[e];
    }
    __syncthreads();
    if (warp == 0) {
        float r[NE];
#pragma unroll
        for (int e = 0; e < NE; e++) r[e] = wsum[lane][e];
#pragma unroll
        for (int off = 16; off; off >>= 1)
#pragma unroll
            for (int e = 0; e < NE; e++) r[e] += __shfl_xor_sync(0xffffffffu, r[e], off);
        if (lane == 0 && aux_out != nullptr) {
            float aux = 0.0f;
            const float invT = 1.0f / (float)T_TOK;
#pragma unroll
            for (int e = 0; e < NE; e++)
                aux += ((float)total[e] * invT) * (r[e] * invT);
            *aux_out = (float)NE * aux;
        }
    }
}

// ---------------- HMMA gathered expert GEMM ----------------------
// block 128x128x32, 8 warps (4 M x 2 N), warp tile 32x64, 4-stage pipe.
// single-pass fp16, fp32 accum.
#define GBM 128
#define GBN 128
#define GBK 32
#define NITER (DIM / GBK)          // 32
#define ATILE 8192                 // 128 rows x 32 fp16
#define BTILE 8192
#define STAGE_BYTES (ATILE + BTILE)   // 16384
#define NSTAGE 4
#define SMEM_DATA0 1024
#define SMEM_GEMM (SMEM_DATA0 + NSTAGE * STAGE_BYTES)   // 66560

__device__ __forceinline__ uint32_t sw_off(int row, int kb) {
    return (uint32_t)(row * 64 + ((kb ^ ((row >> 1) & 3)) << 4));
}

__global__ void __launch_bounds__(256, 2) moe_hmma_kernel(
        const float* __restrict__ bias, float* __restrict__ out) {
    int e    = blockIdx.z;
    int m    = g_m[e];
    int row0 = blockIdx.y * GBM;
    if (row0 >= m) return;
    int col0 = blockIdx.x * GBN;

    extern __shared__ char smem[];
    uint32_t sb = smem_u32(smem);
    int tid  = threadIdx.x;
    int wid  = tid >> 5;
    int lane = tid & 31;
    int warp_m = wid & 3;       // m offset *32
    int warp_n = wid >> 2;      // n offset *64

    int*   stok  = reinterpret_cast<int*>(smem);          // [128]
    float* sprob = reinterpret_cast<float*>(smem + 512);  // [128]

    if (tid < GBM) {
        int gr  = row0 + tid;
        int tok = (gr < m) ? g_tokens[e * CAP + gr] : 0;
        stok[tid]  = tok;
        sprob[tid] = (gr < m) ? g_topprob[tok] : 0.0f;
    }
    __syncthreads();

    const __half* wt = g_wt + ((size_t)e * DIM + col0) * DIM;

    int r0 = tid >> 2, k0 = tid & 3;
    uint32_t d0 = sw_off(r0, k0);
    uint32_t d1 = sw_off(r0 + 64, k0);
    size_t a0row = (size_t)stok[r0] * DIM;
    size_t a1row = (size_t)stok[r0 + 64] * DIM;
    size_t b0row = (size_t)r0 * DIM;
    size_t b1row = (size_t)(r0 + 64) * DIM;

#define ISSUE_STAGE(S, KC0)                                                   \
    do {                                                                      \
        uint32_t st = sb + SMEM_DATA0 + (uint32_t)(S) * STAGE_BYTES;          \
        int ka = (KC0) + k0 * 8;                                              \
        cpasync16(st + d0,         g_xh + a0row + ka);                        \
        cpasync16(st + d1,         g_xh + a1row + ka);                        \
        cpasync16(st + ATILE + d0, wt + b0row + ka);                          \
        cpasync16(st + ATILE + d1, wt + b1row + ka);                          \
        cp_commit();                                                          \
    } while (0)

    int q = lane >> 3, r = lane & 7;
    uint32_t a_off[2][2], b_off[4][2];
#pragma unroll
    for (int mt = 0; mt < 2; mt++)
#pragma unroll
        for (int ks = 0; ks < 2; ks++) {
            int mm = warp_m * 32 + mt * 16 + (q & 1) * 8 + r;
            int kb = ks * 2 + (q >> 1);
            a_off[mt][ks] = sw_off(mm, kb);
        }
#pragma unroll
    for (int nt2 = 0; nt2 < 4; nt2++)
#pragma unroll
        for (int ks = 0; ks < 2; ks++) {
            int nn = warp_n * 64 + nt2 * 16 + (q & 1) * 8 + r;
            int kb = ks * 2 + (q >> 1);
            b_off[nt2][ks] = sw_off(nn, kb);
        }

    float acc[2][8][4];
#pragma unroll
    for (int mt = 0; mt < 2; mt++)
#pragma unroll
        for (int nt = 0; nt < 8; nt++)
#pragma unroll
            for (int j = 0; j < 4; j++) acc[mt][nt][j] = 0.0f;

    ISSUE_STAGE(0, 0);
    ISSUE_STAGE(1, GBK);
    ISSUE_STAGE(2, 2 * GBK);

    int stage = 0;
    for (int c = 0; c < NITER; c++) {
        cp_wait2();
        __syncthreads();
        if (c + 3 < NITER) {
            int s3 = stage + 3;
            if (s3 >= NSTAGE) s3 -= NSTAGE;
            ISSUE_STAGE(s3, (c + 3) * GBK);
        }

        uint32_t st = sb + SMEM_DATA0 + (uint32_t)stage * STAGE_BYTES;
#pragma unroll
        for (int ks = 0; ks < 2; ks++) {
            uint32_t ah[2][4];
#pragma unroll
            for (int mt = 0; mt < 2; mt++)
                LDSM4(ah[mt][0], ah[mt][1], ah[mt][2], ah[mt][3], st + a_off[mt][ks]);
#pragma unroll
            for (int nt2 = 0; nt2 < 4; nt2++) {
                uint32_t t0, t1, t2, t3;
                LDSM4(t0, t1, t2, t3, st + ATILE + b_off[nt2][ks]);
#pragma unroll
                for (int mt = 0; mt < 2; mt++) {
                    MMA16816(acc[mt][nt2 * 2],     ah[mt], t0, t2);
                    MMA16816(acc[mt][nt2 * 2 + 1], ah[mt], t1, t3);
                }
            }
        }
        stage++;
        if (stage >= NSTAGE) stage -= NSTAGE;
    }

    int tq = lane >> 2;
    int tr = lane & 3;
    const float* be = bias + (size_t)e * DIM;
#pragma unroll
    for (int nt = 0; nt < 8; nt++) {
        int col = col0 + warp_n * 64 + nt * 8 + tr * 2;
        float2 bb = *reinterpret_cast<const float2*>(be + col);
#pragma unroll
        for (int mt = 0; mt < 2; mt++) {
#pragma unroll
            for (int h = 0; h < 2; h++) {
                int rw = warp_m * 32 + mt * 16 + h * 8 + tq;
                int gr = row0 + rw;
                if (gr < m) {
                    int   tok = stok[rw];
                    float p   = sprob[rw];
                    float2 o;
                    o.x = (acc[mt][nt][h * 2 + 0] + bb.x) * p;
                    o.y = (acc[mt][nt][h * 2 + 1] + bb.y) * p;
                    *reinterpret_cast<float2*>(out + (size_t)tok * DIM + col) = o;
                }
            }
        }
    }
}

// ---------------- launch ----------------
extern "C" void kernel_launch(void* const* d_in, const int* in_sizes, int n_in,
                              void* d_out, int out_size) {
    const float* x  = (const float*)d_in[0];   // [T, D]
    const float* Wg = (const float*)d_in[1];   // [D, E]
    const float* bg = (const float*)d_in[2];   // [E]
    const float* W  = (const float*)d_in[3];   // [E, D, D]
    const float* b  = (const float*)d_in[4];   // [E, D]
    float* out = (float*)d_out;

    // fused prep: W^T fp16 + gating/x-convert + zero(out)
    prep_kernel<<<PREP_BLOCKS, 256>>>(x, Wg, bg, W, out);

    // routing scan + aux loss
    float* aux_out = (out_size > T_TOK * DIM) ? (out + (size_t)T_TOK * DIM) : nullptr;
    route_kernel<<<1, 1024>>>(aux_out);

    // HMMA gathered expert GEMM (single-pass fp16)
    cudaFuncSetAttribute(moe_hmma_kernel,
                         cudaFuncAttributeMaxDynamicSharedMemorySize, SMEM_GEMM);
    dim3 grid(DIM / GBN, (CAP + GBM - 1) / GBM, NE);
    moe_hmma_kernel<<<grid, 256, SMEM_GEMM>>>(b, out);
}

// round 7
// speedup vs baseline: 4.2874x; 1.3725x over previous
#include <cuda_runtime.h>
#include <cuda_fp16.h>
#include <cstdint>

#define T_TOK 4096
#define DIM   1024
#define NE    8
#define CAP   640   // int(1.25 * 4096 / 8)

// ---------------- scratch (no cudaMalloc allowed) ----------------
__device__ int   g_topidx[T_TOK];
__device__ float g_topprob[T_TOK];
__device__ float g_probs[T_TOK * NE];
__device__ int   g_tokens[NE * CAP];
__device__ int   g_m[NE];

// fp16 operands
__device__ __half g_xh[T_TOK * DIM];         // 8 MB   x fp16 [t][k]
__device__ __half g_wh[NE * DIM * DIM];      // 16 MB  W fp16 [e][k][n]  (native layout!)

// ---------------- helpers ----------------
__device__ __forceinline__ uint32_t smem_u32(const void* p) {
    uint32_t a;
    asm("{ .reg .u64 t; cvta.to.shared.u64 t, %1; cvt.u32.u64 %0, t; }" : "=r"(a) : "l"(p));
    return a;
}
__device__ __forceinline__ void cpasync16(uint32_t dst, const void* src) {
    asm volatile("cp.async.cg.shared.global [%0], [%1], 16;"
                 :: "r"(dst), "l"(__cvta_generic_to_global(src)) : "memory");
}
__device__ __forceinline__ void cp_commit() {
    asm volatile("cp.async.commit_group;" ::: "memory");
}
__device__ __forceinline__ void cp_wait2() {
    asm volatile("cp.async.wait_group 2;" ::: "memory");
}
#define LDSM4(r0, r1, r2, r3, a)                                             \
    asm volatile("ldmatrix.sync.aligned.m8n8.x4.shared.b16 {%0,%1,%2,%3}, [%4];" \
                 : "=r"(r0), "=r"(r1), "=r"(r2), "=r"(r3) : "r"(a))
#define LDSM4T(r0, r1, r2, r3, a)                                            \
    asm volatile("ldmatrix.sync.aligned.m8n8.x4.trans.shared.b16 {%0,%1,%2,%3}, [%4];" \
                 : "=r"(r0), "=r"(r1), "=r"(r2), "=r"(r3) : "r"(a))
#define MMA16816(d, a, b0v, b1v)                                             \
    asm volatile("mma.sync.aligned.m16n8k16.row.col.f32.f16.f16.f32 "        \
                 "{%0,%1,%2,%3},{%4,%5,%6,%7},{%8,%9},{%0,%1,%2,%3};"        \
                 : "+f"((d)[0]), "+f"((d)[1]), "+f"((d)[2]), "+f"((d)[3])    \
                 : "r"((a)[0]), "r"((a)[1]), "r"((a)[2]), "r"((a)[3]),       \
                   "r"(b0v), "r"(b1v))

// ================= prep kernel =================
// blocks [0, GB)            : gating + x fp16 convert (2 tok / warp)
// blocks [GB, GB+WB)        : W fp32 -> fp16 streaming convert (no transpose)
// blocks [GB+WB, GB+WB+ZB)  : zero out[16MB]
#define PREP_GBLKS 256
#define PREP_WBLKS 1024
#define PREP_ZBLKS 512
#define PREP_BLOCKS (PREP_GBLKS + PREP_WBLKS + PREP_ZBLKS)

__global__ void __launch_bounds__(256) prep_kernel(
        const float* __restrict__ x,  const float* __restrict__ Wg,
        const float* __restrict__ bg, const float* __restrict__ W,
        float* __restrict__ out) {
    int bid = blockIdx.x;
    int tid = threadIdx.x;

    if (bid < PREP_GBLKS) {
        // ---- gating + x fp16 convert ----
        int warp = bid * 8 + (tid >> 5);
        int lane = tid & 31;
        int t0 = warp * 2, t1 = warp * 2 + 1;

        const float4* x0 = reinterpret_cast<const float4*>(x + (size_t)t0 * DIM);
        const float4* x1 = reinterpret_cast<const float4*>(x + (size_t)t1 * DIM);
        float a0[NE], a1[NE];
#pragma unroll
        for (int e = 0; e < NE; e++) { a0[e] = 0.0f; a1[e] = 0.0f; }

#pragma unroll
        for (int j = 0; j < 8; j++) {
            int d = j * 128 + lane * 4;
            float4 v0 = x0[d >> 2];
            float4 v1 = x1[d >> 2];
            float f0[4] = {v0.x, v0.y, v0.z, v0.w};
            float f1[4] = {v1.x, v1.y, v1.z, v1.w};
            __half h0[4], h1[4];
#pragma unroll
            for (int i = 0; i < 4; i++) {
                h0[i] = __float2half(f0[i]);
                h1[i] = __float2half(f1[i]);
                const float4* wg4 = reinterpret_cast<const float4*>(Wg + (size_t)(d + i) * NE);
                float4 w0 = wg4[0];
                float4 w1 = wg4[1];
                a0[0] += f0[i] * w0.x; a0[1] += f0[i] * w0.y;
                a0[2] += f0[i] * w0.z; a0[3] += f0[i] * w0.w;
                a0[4] += f0[i] * w1.x; a0[5] += f0[i] * w1.y;
                a0[6] += f0[i] * w1.z; a0[7] += f0[i] * w1.w;
                a1[0] += f1[i] * w0.x; a1[1] += f1[i] * w0.y;
                a1[2] += f1[i] * w0.z; a1[3] += f1[i] * w0.w;
                a1[4] += f1[i] * w1.x; a1[5] += f1[i] * w1.y;
                a1[6] += f1[i] * w1.z; a1[7] += f1[i] * w1.w;
            }
            *reinterpret_cast<uint2*>(g_xh + (size_t)t0 * DIM + d) = *reinterpret_cast<uint2*>(h0);
            *reinterpret_cast<uint2*>(g_xh + (size_t)t1 * DIM + d) = *reinterpret_cast<uint2*>(h1);
        }
#pragma unroll
        for (int e = 0; e < NE; e++) {
#pragma unroll
            for (int off = 16; off; off >>= 1) {
                a0[e] += __shfl_xor_sync(0xffffffffu, a0[e], off);
                a1[e] += __shfl_xor_sync(0xffffffffu, a1[e], off);
            }
        }
        if (lane == 0) {
#pragma unroll
            for (int tt = 0; tt < 2; tt++) {
                float* acc = tt ? a1 : a0;
                int t = tt ? t1 : t0;
                float l[NE], p[NE];
                float mx = -1e30f;
                int arg = 0;
#pragma unroll
                for (int e = 0; e < NE; e++) l[e] = acc[e] + bg[e];
#pragma unroll
                for (int e = 0; e < NE; e++) {
                    if (l[e] > mx) { mx = l[e]; arg = e; }
                }
                float s = 0.0f;
#pragma unroll
                for (int e = 0; e < NE; e++) { p[e] = expf(l[e] - mx); s += p[e]; }
                float inv = 1.0f / s;
#pragma unroll
                for (int e = 0; e < NE; e++) g_probs[(size_t)t * NE + e] = p[e] * inv;
                g_topidx[t]  = arg;
                g_topprob[t] = p[arg] * inv;
            }
        }
        return;
    }
    if (bid < PREP_GBLKS + PREP_WBLKS) {
        // ---- W fp32 -> fp16 streaming (8 float4 per thread) ----
        int wb = bid - PREP_GBLKS;
        const float4* src = reinterpret_cast<const float4*>(W);
        uint2* dst = reinterpret_cast<uint2*>(g_wh);
        size_t u0 = (size_t)wb * 2048 + tid;
#pragma unroll
        for (int i = 0; i < 8; i++) {
            size_t u = u0 + (size_t)i * 256;
            float4 v = src[u];
            __half2 lo = __floats2half2_rn(v.x, v.y);
            __half2 hi = __floats2half2_rn(v.z, v.w);
            uint2 o;
            o.x = *reinterpret_cast<uint32_t*>(&lo);
            o.y = *reinterpret_cast<uint32_t*>(&hi);
            dst[u] = o;
        }
        return;
    }
    // ---- zero out (full 16 MB, 8 float4 per thread) ----
    {
        int zb = bid - PREP_GBLKS - PREP_WBLKS;
        float4 z = make_float4(0.f, 0.f, 0.f, 0.f);
        float4* o4 = reinterpret_cast<float4*>(out) + (size_t)zb * 2048 + tid;
#pragma unroll
        for (int j = 0; j < 8; j++) o4[j * 256] = z;
    }
}

// ---------------- routing scan (shfl-based) ----------------------
__global__ void __launch_bounds__(1024) route_kernel(float* __restrict__ aux_out) {
    __shared__ int   wtot[32][NE];
    __shared__ float wsum[32][NE];
    int tid  = threadIdx.x;
    int lane = tid & 31;
    int warp = tid >> 5;

    int c[NE];
#pragma unroll
    for (int e = 0; e < NE; e++) c[e] = 0;
    int myexp[4];
#pragma unroll
    for (int j = 0; j < 4; j++) {
        int t = tid * 4 + j;
        int e = g_topidx[t];
        myexp[j] = e;
        c[e]++;
    }
    int inc[NE];
#pragma unroll
    for (int e = 0; e < NE; e++) inc[e] = c[e];
#pragma unroll
    for (int off = 1; off < 32; off <<= 1) {
#pragma unroll
        for (int e = 0; e < NE; e++) {
            int v = __shfl_up_sync(0xffffffffu, inc[e], off);
            if (lane >= off) inc[e] += v;
        }
    }
    if (lane == 31) {
#pragma unroll
        for (int e = 0; e < NE; e++) wtot[warp][e] = inc[e];
    }
    __syncthreads();
    if (warp == 0) {
        int v[NE];
#pragma unroll
        for (int e = 0; e < NE; e++) v[e] = wtot[lane][e];
#pragma unroll
        for (int off = 1; off < 32; off <<= 1) {
#pragma unroll
            for (int e = 0; e < NE; e++) {
                int u = __shfl_up_sync(0xffffffffu, v[e], off);
                if (lane >= off) v[e] += u;
            }
        }
#pragma unroll
        for (int e = 0; e < NE; e++) wtot[lane][e] = v[e];
    }
    __syncthreads();

    int total[NE], run[NE];
#pragma unroll
    for (int e = 0; e < NE; e++) {
        total[e] = wtot[31][e];
        run[e]   = (warp ? wtot[warp - 1][e] : 0) + inc[e] - c[e];
    }
#pragma unroll
    for (int j = 0; j < 4; j++) {
        int t = tid * 4 + j;
        int e = myexp[j];
        run[e]++;
        int pos = run[e];
        if (pos <= CAP) g_tokens[e * CAP + pos - 1] = t;
    }
    if (tid < NE) g_m[tid] = (total[tid] < CAP) ? total[tid] : CAP;

    float s[NE];
#pragma unroll
    for (int e = 0; e < NE; e++) s[e] = 0.0f;
#pragma unroll
    for (int j = 0; j < 4; j++) {
        const float4* p4 = reinterpret_cast<const float4*>(g_probs + (size_t)(tid * 4 + j) * NE);
        float4 a = p4[0], bb = p4[1];
        s[0] += a.x; s[1] += a.y; s[2] += a.z; s[3] += a.w;
        s[4] += bb.x; s[5] += bb.y; s[6] += bb.z; s[7] += bb.w;
    }
#pragma unroll
    for (int off = 16; off; off >>= 1)
#pragma unroll
        for (int e = 0; e < NE; e++) s[e] += __shfl_xor_sync(0xffffffffu, s[e], off);
    if (lane == 0) {
#pragma unroll
        for (int e = 0; e < NE; e++) wsum[warp][e] = s[e];
    }
    __syncthreads();
    if (warp == 0) {
        float r[NE];
#pragma unroll
        for (int e = 0; e < NE; e++) r[e] = wsum[lane][e];
#pragma unroll
        for (int off = 16; off; off >>= 1)
#pragma unroll
            for (int e = 0; e < NE; e++) r[e] += __shfl_xor_sync(0xffffffffu, r[e], off);
        if (lane == 0 && aux_out != nullptr) {
            float aux = 0.0f;
            const float invT = 1.0f / (float)T_TOK;
#pragma unroll
            for (int e = 0; e < NE; e++)
                aux += ((float)total[e] * invT) * (r[e] * invT);
            *aux_out = (float)NE * aux;
        }
    }
}

// ---------------- HMMA gathered expert GEMM ----------------------
// block 128x128x32, 8 warps (4 M x 2 N), warp tile 32x64, 4-stage pipe.
// A: gathered x rows [m][k] (64B rows, XOR swizzle), plain ldmatrix.
// B: W native [k][n] tile (256B rows, chunk-XOR swizzle), ldmatrix.trans.
#define GBM 128
#define GBN 128
#define GBK 32
#define NITER (DIM / GBK)          // 32
#define ATILE 8192                 // 128 rows x 32 fp16
#define BTILE 8192                 // 32 rows x 128 fp16
#define STAGE_BYTES (ATILE + BTILE)   // 16384
#define NSTAGE 4
#define SMEM_DATA0 1024
#define SMEM_GEMM (SMEM_DATA0 + NSTAGE * STAGE_BYTES)   // 66560

// A tile: row-major [m][32], 64B/row; chunk xor (row>>1)&3
__device__ __forceinline__ uint32_t sw_a(int row, int kb) {
    return (uint32_t)(row * 64 + ((kb ^ ((row >> 1) & 3)) << 4));
}
// B tile: row-major [k][128], 256B/row; 16B-chunk nc xor (k&7) on low 3 bits
__device__ __forceinline__ uint32_t sw_b(int k, int nc) {
    return (uint32_t)(k * 256 + ((((nc & 7) ^ (k & 7)) | (nc & 8)) << 4));
}

__global__ void __launch_bounds__(256, 2) moe_hmma_kernel(
        const float* __restrict__ bias, float* __restrict__ out) {
    int e    = blockIdx.z;
    int m    = g_m[e];
    int row0 = blockIdx.y * GBM;
    if (row0 >= m) return;
    int col0 = blockIdx.x * GBN;

    extern __shared__ char smem[];
    uint32_t sb = smem_u32(smem);
    int tid  = threadIdx.x;
    int wid  = tid >> 5;
    int lane = tid & 31;
    int warp_m = wid & 3;       // m offset *32
    int warp_n = wid >> 2;      // n offset *64

    int*   stok  = reinterpret_cast<int*>(smem);          // [128]
    float* sprob = reinterpret_cast<float*>(smem + 512);  // [128]

    if (tid < GBM) {
        int gr  = row0 + tid;
        int tok = (gr < m) ? g_tokens[e * CAP + gr] : 0;
        stok[tid]  = tok;
        sprob[tid] = (gr < m) ? g_topprob[tok] : 0.0f;
    }
    __syncthreads();

    const __half* wbase = g_wh + (size_t)e * DIM * DIM + col0;   // [k][n] slab

    // A loader: rows tid/4 and tid/4+64, k-chunk tid%4
    int ar = tid >> 2, ak = tid & 3;
    uint32_t ad0 = sw_a(ar, ak);
    uint32_t ad1 = sw_a(ar + 64, ak);
    size_t a0row = (size_t)stok[ar] * DIM;
    size_t a1row = (size_t)stok[ar + 64] * DIM;
    // B loader: k-row tid/8, chunks tid%8 and 8+(tid%8)
    int bk = tid >> 3, bn = tid & 7;
    uint32_t bd0 = sw_b(bk, bn);
    uint32_t bd1 = sw_b(bk, bn + 8);

#define ISSUE_STAGE(S, KC0)                                                   \
    do {                                                                      \
        uint32_t st = sb + SMEM_DATA0 + (uint32_t)(S) * STAGE_BYTES;          \
        cpasync16(st + ad0,         g_xh + a0row + (KC0) + ak * 8);           \
        cpasync16(st + ad1,         g_xh + a1row + (KC0) + ak * 8);           \
        const __half* wrow = wbase + (size_t)((KC0) + bk) * DIM;              \
        cpasync16(st + ATILE + bd0, wrow + bn * 8);                           \
        cpasync16(st + ATILE + bd1, wrow + bn * 8 + 64);                      \
        cp_commit();                                                          \
    } while (0)

    // A ldmatrix lane offsets (plain, x4: m16 x k16)
    int q = lane >> 3, r = lane & 7;
    uint32_t a_off[2][2];
#pragma unroll
    for (int mt = 0; mt < 2; mt++)
#pragma unroll
        for (int ks = 0; ks < 2; ks++) {
            int mm = warp_m * 32 + mt * 16 + (q & 1) * 8 + r;
            int kb = ks * 2 + (q >> 1);
            a_off[mt][ks] = sw_a(mm, kb);
        }
    // B ldmatrix.trans lane offsets: matrix g=lane/8: k_sub=(g&1)*8, n_sub=(g>>1)*8
    uint32_t b_off[4][2];
#pragma unroll
    for (int nt2 = 0; nt2 < 4; nt2++)
#pragma unroll
        for (int ks = 0; ks < 2; ks++) {
            int kk = ks * 16 + (q & 1) * 8 + r;          // k row
            int nc = warp_n * 8 + nt2 * 2 + (q >> 1);    // 16B chunk along n
            b_off[nt2][ks] = sw_b(kk, nc);
        }

    float acc[2][8][4];
#pragma unroll
    for (int mt = 0; mt < 2; mt++)
#pragma unroll
        for (int nt = 0; nt < 8; nt++)
#pragma unroll
            for (int j = 0; j < 4; j++) acc[mt][nt][j] = 0.0f;

    ISSUE_STAGE(0, 0);
    ISSUE_STAGE(1, GBK);
    ISSUE_STAGE(2, 2 * GBK);

    int stage = 0;
    for (int c = 0; c < NITER; c++) {
        cp_wait2();
        __syncthreads();
        if (c + 3 < NITER) {
            int s3 = stage + 3;
            if (s3 >= NSTAGE) s3 -= NSTAGE;
            ISSUE_STAGE(s3, (c + 3) * GBK);
        }

        uint32_t st = sb + SMEM_DATA0 + (uint32_t)stage * STAGE_BYTES;
#pragma unroll
        for (int ks = 0; ks < 2; ks++) {
            uint32_t ah[2][4];
#pragma unroll
            for (int mt = 0; mt < 2; mt++)
                LDSM4(ah[mt][0], ah[mt][1], ah[mt][2], ah[mt][3], st + a_off[mt][ks]);
#pragma unroll
            for (int nt2 = 0; nt2 < 4; nt2++) {
                uint32_t t0, t1, t2, t3;
                LDSM4T(t0, t1, t2, t3, st + ATILE + b_off[nt2][ks]);
#pragma unroll
                for (int mt = 0; mt < 2; mt++) {
                    MMA16816(acc[mt][nt2 * 2],     ah[mt], t0, t1);
                    MMA16816(acc[mt][nt2 * 2 + 1], ah[mt], t2, t3);
                }
            }
        }
        stage++;
        if (stage >= NSTAGE) stage -= NSTAGE;
    }

    int tq = lane >> 2;
    int tr = lane & 3;
    const float* be = bias + (size_t)e * DIM;
#pragma unroll
    for (int nt = 0; nt < 8; nt++) {
        int col = col0 + warp_n * 64 + nt * 8 + tr * 2;
        float2 bb = *reinterpret_cast<const float2*>(be + col);
#pragma unroll
        for (int mt = 0; mt < 2; mt++) {
#pragma unroll
            for (int h = 0; h < 2; h++) {
                int rw = warp_m * 32 + mt * 16 + h * 8 + tq;
                int gr = row0 + rw;
                if (gr < m) {
                    int   tok = stok[rw];
                    float p   = sprob[rw];
                    float2 o;
                    o.x = (acc[mt][nt][h * 2 + 0] + bb.x) * p;
                    o.y = (acc[mt][nt][h * 2 + 1] + bb.y) * p;
                    *reinterpret_cast<float2*>(out + (size_t)tok * DIM + col) = o;
                }
            }
        }
    }
}

// ---------------- launch ----------------
extern "C" void kernel_launch(void* const* d_in, const int* in_sizes, int n_in,
                              void* d_out, int out_size) {
    const float* x  = (const float*)d_in[0];   // [T, D]
    const float* Wg = (const float*)d_in[1];   // [D, E]
    const float* bg = (const float*)d_in[2];   // [E]
    const float* W  = (const float*)d_in[3];   // [E, D, D]
    const float* b  = (const float*)d_in[4];   // [E, D]
    float* out = (float*)d_out;

    // fused prep: gating/x-convert + W fp16 stream-convert + zero(out)
    prep_kernel<<<PREP_BLOCKS, 256>>>(x, Wg, bg, W, out);

    // routing scan + aux loss
    float* aux_out = (out_size > T_TOK * DIM) ? (out + (size_t)T_TOK * DIM) : nullptr;
    route_kernel<<<1, 1024>>>(aux_out);

    // HMMA gathered expert GEMM (single-pass fp16, trans-B)
    cudaFuncSetAttribute(moe_hmma_kernel,
                         cudaFuncAttributeMaxDynamicSharedMemorySize, SMEM_GEMM);
    dim3 grid(DIM / GBN, (CAP + GBM - 1) / GBM, NE);
    moe_hmma_kernel<<<grid, 256, SMEM_GEMM>>>(b, out);
}